// round 12
// baseline (speedup 1.0000x reference)
#include <cuda_runtime.h>
#include <cuda_bf16.h>
#include <math.h>
#include <stdint.h>

#define NROI 512
#define NCH 512
#define HF 37
#define WF 50
#define NCLS 11
#define POOLDIM 25088   // NCH * 7 * 7
#define FCDIM 4096
#define NSPLIT 8

// ---------------- scratch (device globals; no allocation allowed) ----------
__device__ __nv_bfloat16 g_poolh[(size_t)NROI * POOLDIM];
__device__ __nv_bfloat16 g_pooll[(size_t)NROI * POOLDIM];
__device__ __nv_bfloat16 g_W1h[(size_t)POOLDIM * FCDIM];
__device__ __nv_bfloat16 g_W1l[(size_t)POOLDIM * FCDIM];
__device__ __nv_bfloat16 g_W2h[(size_t)FCDIM * FCDIM];
__device__ __nv_bfloat16 g_W2l[(size_t)FCDIM * FCDIM];
__device__ __nv_bfloat16 g_fc1h[(size_t)NROI * FCDIM];
__device__ __nv_bfloat16 g_fc1l[(size_t)NROI * FCDIM];
__device__ float g_part[(size_t)NSPLIT * NROI * FCDIM];   // split-K partials (64MB)
__device__ float g_fc7[(size_t)NROI * FCDIM];
__device__ float g_Wt[55 * FCDIM];
__device__ float g_ls[NROI * 55];
__device__ float g_bbox[NROI * 44];
__device__ float g_prob[NROI * 11];

__device__ __forceinline__ float neg_inf() { return __int_as_float(0xff800000); }
__device__ __forceinline__ float pos_inf() { return __int_as_float(0x7f800000); }

// ---------------- streams/events, created once at static init --------------
struct StreamPack {
    cudaStream_t s1, s2;
    cudaEvent_t ev0, ev1, ev2, ev3;
    StreamPack() {
        cudaStreamCreateWithFlags(&s1, cudaStreamNonBlocking);
        cudaStreamCreateWithFlags(&s2, cudaStreamNonBlocking);
        cudaEventCreateWithFlags(&ev0, cudaEventDisableTiming);
        cudaEventCreateWithFlags(&ev1, cudaEventDisableTiming);
        cudaEventCreateWithFlags(&ev2, cudaEventDisableTiming);
        cudaEventCreateWithFlags(&ev3, cudaEventDisableTiming);
    }
};
static StreamPack g_sp;

// ========================= PTX helpers (baseline ISA only) =================
__device__ __forceinline__ uint32_t smem_u32(const void* p) {
    uint32_t a;
    asm("{ .reg .u64 t; cvta.to.shared.u64 t, %1; cvt.u32.u64 %0, t; }" : "=r"(a) : "l"(p));
    return a;
}
__device__ __forceinline__ uint32_t pack_bf16x2(float lo, float hi) {
    uint32_t r;
    asm("cvt.rn.bf16x2.f32 %0, %1, %2;" : "=r"(r) : "f"(hi), "f"(lo));
    return r;
}

#define LDM_X4(r, a) \
    asm volatile("ldmatrix.sync.aligned.m8n8.x4.shared.b16 {%0,%1,%2,%3}, [%4];" \
        : "=r"((r)[0]), "=r"((r)[1]), "=r"((r)[2]), "=r"((r)[3]) : "r"(a))
#define LDM_X4T(r, a) \
    asm volatile("ldmatrix.sync.aligned.m8n8.x4.trans.shared.b16 {%0,%1,%2,%3}, [%4];" \
        : "=r"((r)[0]), "=r"((r)[1]), "=r"((r)[2]), "=r"((r)[3]) : "r"(a))

__device__ __forceinline__ void mma16816(float* c, const uint32_t* a, uint32_t b0, uint32_t b1) {
    asm volatile(
        "mma.sync.aligned.m16n8k16.row.col.f32.bf16.bf16.f32 "
        "{%0,%1,%2,%3}, {%4,%5,%6,%7}, {%8,%9}, {%0,%1,%2,%3};"
        : "+f"(c[0]), "+f"(c[1]), "+f"(c[2]), "+f"(c[3])
        : "r"(a[0]), "r"(a[1]), "r"(a[2]), "r"(a[3]), "r"(b0), "r"(b1));
}

#define CP16(dst, src) \
    asm volatile("cp.async.cg.shared.global [%0], [%1], 16;" :: "r"(dst), "l"(src))
#define CP_COMMIT() asm volatile("cp.async.commit_group;" ::: "memory")
#define CP_WAIT0() asm volatile("cp.async.wait_group 0;" ::: "memory")
#define CP_WAIT1() asm volatile("cp.async.wait_group 1;" ::: "memory")
#define CP_WAIT2() asm volatile("cp.async.wait_group 2;" ::: "memory")

// ========================= split-bf16 HMMA GEMM (R7 core + split-K) ========
// Partial[z] = A[:, zKs:(z+1)Ks] * B[zKs:(z+1)Ks, :]; 3-pass hh+hl+lh.
// Tile 128x128x32, 512 threads (16 warps, warp tile 32x32), 4-stage cp.async.
// LDSM/MMA interleave: (ah,bh) -> hh MMAs -> (al,bl) -> hl,lh MMAs.
#define ST_AHI 0
#define ST_ALO 8192
#define ST_BHI 16384
#define ST_BLO 24576
#define STAGE_SZ 32768
#define NSTAGE 4
#define GEMM_SMEM (NSTAGE * STAGE_SZ)
#define GEMM_THREADS 512

__device__ __forceinline__ uint32_t aoff(int m, int k) {
    return (uint32_t)(m * 64 + ((((k >> 3) ^ ((m >> 1) ^ (m >> 3))) & 3) << 4) + (k & 7) * 2);
}
__device__ __forceinline__ uint32_t boff(int k, int n) {
    return (uint32_t)(k * 256 + ((((n >> 3) ^ (k & 7)) & 15) << 4) + (n & 7) * 2);
}

__global__ void __launch_bounds__(GEMM_THREADS, 1)
mma_fc_kernel(const __nv_bfloat16* __restrict__ Ah, const __nv_bfloat16* __restrict__ Al,
              const __nv_bfloat16* __restrict__ Bh, const __nv_bfloat16* __restrict__ Bl,
              float* __restrict__ Cpart, int N, int Ktot, int Ks) {
    extern __shared__ char smem[];
    uint32_t sbase = smem_u32(smem);
    const int t = threadIdx.x;
    const int lane = t & 31;
    const int wid = t >> 5;
    const int wy = wid & 3;
    const int wx = wid >> 2;
    const int m0 = blockIdx.y * 128;
    const int n0 = blockIdx.x * 128;
    const int kbase = blockIdx.z * Ks;

    const int am = t >> 2;
    const int ak = (t & 3) * 8;
    const int bk = t >> 4;
    const int bn = (t & 15) * 8;

    const uint32_t oA = ST_AHI + aoff(am, ak);
    const uint32_t oB = ST_BHI + boff(bk, bn);

    const int nit = Ks / 32;

    float acc[2][4][4];
    #pragma unroll
    for (int i = 0; i < 2; i++)
        #pragma unroll
        for (int j = 0; j < 4; j++)
            #pragma unroll
            for (int e = 0; e < 4; e++) acc[i][j][e] = 0.0f;

#define ISSUE(stg, kg) do {                                                    \
        uint32_t s_ = sbase + (uint32_t)(stg) * STAGE_SZ;                      \
        const __nv_bfloat16* ah_ = Ah + (size_t)(m0 + am) * Ktot + (kg) + ak;  \
        const __nv_bfloat16* al_ = Al + (size_t)(m0 + am) * Ktot + (kg) + ak;  \
        CP16(s_ + oA, ah_);                                                    \
        CP16(s_ + oA + (ST_ALO - ST_AHI), al_);                                \
        const __nv_bfloat16* bh_ = Bh + (size_t)((kg) + bk) * N + n0 + bn;     \
        const __nv_bfloat16* bl_ = Bl + (size_t)((kg) + bk) * N + n0 + bn;     \
        CP16(s_ + oB, bh_);                                                    \
        CP16(s_ + oB + (ST_BLO - ST_BHI), bl_);                                \
        CP_COMMIT();                                                           \
    } while (0)

    ISSUE(0, kbase);
    ISSUE(1, kbase + 32);
    ISSUE(2, kbase + 64);

    const int arow_l = lane & 15;
    const int khalf = (lane >> 4) << 3;

    int cur = 0, nxt = 3;
    for (int it = 0; it < nit; it++) {
        if (it < nit - 2)      { CP_WAIT2(); }
        else if (it == nit - 2){ CP_WAIT1(); }
        else                   { CP_WAIT0(); }
        __syncthreads();
        if (it + 3 < nit) {
            ISSUE(nxt, kbase + (it + 3) * 32);
            if (++nxt == NSTAGE) nxt = 0;
        }

        uint32_t sA_hi = sbase + (uint32_t)cur * STAGE_SZ + ST_AHI;
        uint32_t sA_lo = sA_hi + (ST_ALO - ST_AHI);
        uint32_t sB_hi = sbase + (uint32_t)cur * STAGE_SZ + ST_BHI;
        uint32_t sB_lo = sB_hi + (ST_BLO - ST_BHI);
        if (++cur == NSTAGE) cur = 0;

        #pragma unroll
        for (int ks = 0; ks < 2; ks++) {
            const int k0 = ks * 16;
            uint32_t ah[2][4], al[2][4], bh[2][4], bl[2][4];
            // --- load only hi fragments first ---
            #pragma unroll
            for (int mi = 0; mi < 2; mi++) {
                int mrow = wy * 32 + mi * 16 + arow_l;
                LDM_X4(ah[mi], sA_hi + aoff(mrow, k0 + khalf));
            }
            #pragma unroll
            for (int nt = 0; nt < 2; nt++) {
                int krow = k0 + (lane & 15);
                int ncol = wx * 32 + nt * 16 + khalf;
                LDM_X4T(bh[nt], sB_hi + boff(krow, ncol));
            }
            // --- hh pass (hides nothing; operands just loaded) ---
            #pragma unroll
            for (int mi = 0; mi < 2; mi++)
                #pragma unroll
                for (int ni = 0; ni < 4; ni++)
                    mma16816(acc[mi][ni], ah[mi], bh[ni >> 1][(ni & 1) * 2],
                             bh[ni >> 1][(ni & 1) * 2 + 1]);
            // --- load lo fragments; latency hides under hh tensor work ---
            #pragma unroll
            for (int mi = 0; mi < 2; mi++) {
                int mrow = wy * 32 + mi * 16 + arow_l;
                LDM_X4(al[mi], sA_lo + aoff(mrow, k0 + khalf));
            }
            #pragma unroll
            for (int nt = 0; nt < 2; nt++) {
                int krow = k0 + (lane & 15);
                int ncol = wx * 32 + nt * 16 + khalf;
                LDM_X4T(bl[nt], sB_lo + boff(krow, ncol));
            }
            // --- hl pass ---
            #pragma unroll
            for (int mi = 0; mi < 2; mi++)
                #pragma unroll
                for (int ni = 0; ni < 4; ni++)
                    mma16816(acc[mi][ni], ah[mi], bl[ni >> 1][(ni & 1) * 2],
                             bl[ni >> 1][(ni & 1) * 2 + 1]);
            // --- lh pass ---
            #pragma unroll
            for (int mi = 0; mi < 2; mi++)
                #pragma unroll
                for (int ni = 0; ni < 4; ni++)
                    mma16816(acc[mi][ni], al[mi], bh[ni >> 1][(ni & 1) * 2],
                             bh[ni >> 1][(ni & 1) * 2 + 1]);
        }
    }

    // ---- epilogue: raw fp32 partial store ----
    float* Cp = Cpart + (size_t)blockIdx.z * (size_t)(gridDim.y * 128) * N;
    #pragma unroll
    for (int mi = 0; mi < 2; mi++) {
        int mrow = m0 + wy * 32 + mi * 16 + (lane >> 2);
        #pragma unroll
        for (int ni = 0; ni < 4; ni++) {
            int ncol = n0 + wx * 32 + ni * 8 + (lane & 3) * 2;
            *(float2*)(Cp + (size_t)mrow * N + ncol) =
                make_float2(acc[mi][ni][0], acc[mi][ni][1]);
            *(float2*)(Cp + (size_t)(mrow + 8) * N + ncol) =
                make_float2(acc[mi][ni][2], acc[mi][ni][3]);
        }
    }
#undef ISSUE
}

// ---------------- split-K reduce: sum partials + bias + relu ---------------
template <int OUT>
__global__ void __launch_bounds__(256) reduce_kernel(
        const float* __restrict__ part, const float* __restrict__ bias,
        float* __restrict__ Cf, __nv_bfloat16* __restrict__ Ch,
        __nv_bfloat16* __restrict__ Cl, int N, int total) {
    int i4 = blockIdx.x * blockDim.x + threadIdx.x;   // float4 index
    if (i4 * 4 >= total) return;
    float4 s = ((const float4*)part)[i4];
    #pragma unroll
    for (int z = 1; z < NSPLIT; z++) {
        float4 p = ((const float4*)(part + (size_t)z * total))[i4];
        s.x += p.x; s.y += p.y; s.z += p.z; s.w += p.w;
    }
    int e = i4 * 4;
    int n = e & (N - 1);
    s.x = fmaxf(s.x + bias[n],     0.0f);
    s.y = fmaxf(s.y + bias[n + 1], 0.0f);
    s.z = fmaxf(s.z + bias[n + 2], 0.0f);
    s.w = fmaxf(s.w + bias[n + 3], 0.0f);
    if (OUT == 0) {
        ((float4*)Cf)[i4] = s;
    } else {
        uint32_t h01 = pack_bf16x2(s.x, s.y);
        uint32_t h23 = pack_bf16x2(s.z, s.w);
        uint32_t l01 = pack_bf16x2(s.x - __uint_as_float(h01 << 16),
                                   s.y - __uint_as_float(h01 & 0xffff0000u));
        uint32_t l23 = pack_bf16x2(s.z - __uint_as_float(h23 << 16),
                                   s.w - __uint_as_float(h23 & 0xffff0000u));
        ((uint2*)Ch)[i4] = make_uint2(h01, h23);
        ((uint2*)Cl)[i4] = make_uint2(l01, l23);
    }
}

// ---------------- 0. fp32 -> bf16 hi/lo split (streaming) -------------------
__global__ void split_kernel(const float* __restrict__ src,
                             __nv_bfloat16* __restrict__ hi,
                             __nv_bfloat16* __restrict__ lo, size_t n4) {
    size_t stride = (size_t)gridDim.x * blockDim.x;
    for (size_t i = (size_t)blockIdx.x * blockDim.x + threadIdx.x; i < n4; i += stride) {
        float4 v = ((const float4*)src)[i];
        uint32_t h0 = pack_bf16x2(v.x, v.y);
        uint32_t h1 = pack_bf16x2(v.z, v.w);
        uint32_t l0 = pack_bf16x2(v.x - __uint_as_float(h0 << 16),
                                  v.y - __uint_as_float(h0 & 0xffff0000u));
        uint32_t l1 = pack_bf16x2(v.z - __uint_as_float(h1 << 16),
                                  v.w - __uint_as_float(h1 & 0xffff0000u));
        ((uint2*)hi)[i] = make_uint2(h0, h1);
        ((uint2*)lo)[i] = make_uint2(l0, l1);
    }
}

// ---------------- 1. ROI max-pool (emits bf16 hi/lo directly) ---------------
__global__ void __launch_bounds__(512) roipool_kernel(const float* __restrict__ feat,
                               const float* __restrict__ rois,
                               const int* __restrict__ roi_idx) {
    int r = blockIdx.x;
    __shared__ int hs[7], he[7], ws[7], we[7];
    if (threadIdx.x == 0) {
        const float RECIP7 = 1.0f / 7.0f;   // matches XLA's x/7 -> x*recip rewrite
        float y1 = rois[r * 4 + 0], x1 = rois[r * 4 + 1];
        float y2 = rois[r * 4 + 2], x2 = rois[r * 4 + 3];
        float sw = rintf(x1 * 0.0625f);
        float ew = rintf(x2 * 0.0625f);
        float sh = rintf(y1 * 0.0625f);
        float eh = rintf(y2 * 0.0625f);
        float rw = fmaxf(ew - sw + 1.0f, 1.0f);
        float rh = fmaxf(eh - sh + 1.0f, 1.0f);
        #pragma unroll
        for (int p = 0; p < 7; p++) {
            float fp = (float)p;
            float h0 = floorf(__fmul_rn(fp * rh, RECIP7)) + sh;
            float h1 = ceilf(__fmul_rn((fp + 1.0f) * rh, RECIP7)) + sh;
            float w0 = floorf(__fmul_rn(fp * rw, RECIP7)) + sw;
            float w1 = ceilf(__fmul_rn((fp + 1.0f) * rw, RECIP7)) + sw;
            hs[p] = (int)fminf(fmaxf(h0, 0.0f), (float)HF);
            he[p] = (int)fminf(fmaxf(h1, 0.0f), (float)HF);
            ws[p] = (int)fminf(fmaxf(w0, 0.0f), (float)WF);
            we[p] = (int)fminf(fmaxf(w1, 0.0f), (float)WF);
        }
    }
    __syncthreads();
    int b = roi_idx[r];
    const float* f = feat + (size_t)b * NCH * HF * WF;
    for (int idx = threadIdx.x; idx < POOLDIM; idx += blockDim.x) {
        int c = idx / 49;
        int rem = idx - c * 49;
        int ph = rem / 7, pw = rem - (rem / 7) * 7;
        int h0 = hs[ph], h1 = he[ph], w0 = ws[pw], w1 = we[pw];
        float m = 0.0f;
        if (h1 > h0 && w1 > w0) {
            m = neg_inf();
            const float* fc_ = f + (size_t)c * (HF * WF);
            for (int y = h0; y < h1; y++)
                for (int x = w0; x < w1; x++)
                    m = fmaxf(m, fc_[y * WF + x]);
        }
        __nv_bfloat16 hb = __float2bfloat16(m);
        g_poolh[(size_t)r * POOLDIM + idx] = hb;
        g_pooll[(size_t)r * POOLDIM + idx] = __float2bfloat16(m - __bfloat162float(hb));
    }
}

// ---------------- 2. head W transpose: g_Wt[55][4096] ----------------------
__global__ void prep_head_kernel(const float* __restrict__ Wloc,
                                 const float* __restrict__ Wsc) {
    int stride = gridDim.x * blockDim.x;
    for (int i = blockIdx.x * blockDim.x + threadIdx.x; i < 55 * FCDIM; i += stride) {
        int col = i >> 12;
        int k = i & (FCDIM - 1);
        g_Wt[i] = (col < 44) ? Wloc[(size_t)k * 44 + col] : Wsc[(size_t)k * 11 + (col - 44)];
    }
}

// ---------------- 3. heads: 2 ROIs per block, warp-per-output --------------
__global__ void __launch_bounds__(256) head_kernel(const float* __restrict__ bloc,
                                                   const float* __restrict__ bsc) {
    __shared__ float4 Fs[2][FCDIM / 4];
    int r0 = blockIdx.x * 2;
    int t = threadIdx.x;
    for (int i = t; i < 2 * (FCDIM / 4); i += 256) {
        int ri = i >> 10, kk = i & 1023;
        Fs[ri][kk] = ((const float4*)g_fc7)[(size_t)(r0 + ri) * (FCDIM / 4) + kk];
    }
    __syncthreads();
    int w = t >> 5, lane = t & 31;
    for (int o = w; o < 110; o += 8) {
        int roi = (o >= 55) ? 1 : 0;
        int col = o - roi * 55;
        const float4* wp = (const float4*)(g_Wt + col * FCDIM);
        float acc = 0.0f;
        for (int kb = lane; kb < FCDIM / 4; kb += 32) {
            float4 f = Fs[roi][kb];
            float4 v = wp[kb];
            acc = fmaf(f.x, v.x, acc);
            acc = fmaf(f.y, v.y, acc);
            acc = fmaf(f.z, v.z, acc);
            acc = fmaf(f.w, v.w, acc);
        }
        #pragma unroll
        for (int of = 16; of > 0; of >>= 1) acc += __shfl_xor_sync(0xffffffffu, acc, of);
        if (lane == 0) {
            float bb = (col < 44) ? bloc[col] : bsc[col - 44];
            g_ls[(r0 + roi) * 55 + col] = acc + bb;
        }
    }
}

// ---------------- 4. bbox decode + clip + softmax ---------------------------
__global__ void post_kernel(const float* __restrict__ rois, float* __restrict__ out) {
    int r = blockIdx.x * blockDim.x + threadIdx.x;
    if (r >= NROI) return;
    float y1 = rois[r * 4 + 0], x1 = rois[r * 4 + 1];
    float y2 = rois[r * 4 + 2], x2 = rois[r * 4 + 3];
    float sh_ = y2 - y1, sw_ = x2 - x1;
    float cy = y1 + 0.5f * sh_, cx = x1 + 0.5f * sw_;
    #pragma unroll
    for (int c = 0; c < NCLS; c++) {
        float dy = g_ls[r * 55 + c * 4 + 0] * 0.1f;
        float dx = g_ls[r * 55 + c * 4 + 1] * 0.1f;
        float dh = g_ls[r * 55 + c * 4 + 2] * 0.2f;
        float dw = g_ls[r * 55 + c * 4 + 3] * 0.2f;
        float ncy = dy * sh_ + cy;
        float ncx = dx * sw_ + cx;
        float nh = expf(dh) * sh_;
        float nw = expf(dw) * sw_;
        float by1 = fminf(fmaxf(ncy - 0.5f * nh, 0.0f), 600.0f);
        float bx1 = fminf(fmaxf(ncx - 0.5f * nw, 0.0f), 800.0f);
        float by2 = fminf(fmaxf(ncy + 0.5f * nh, 0.0f), 600.0f);
        float bx2 = fminf(fmaxf(ncx + 0.5f * nw, 0.0f), 800.0f);
        g_bbox[r * 44 + c * 4 + 0] = by1;
        g_bbox[r * 44 + c * 4 + 1] = bx1;
        g_bbox[r * 44 + c * 4 + 2] = by2;
        g_bbox[r * 44 + c * 4 + 3] = bx2;
        out[r * 44 + c * 4 + 0] = by1;
        out[r * 44 + c * 4 + 1] = bx1;
        out[r * 44 + c * 4 + 2] = by2;
        out[r * 44 + c * 4 + 3] = bx2;
    }
    float sc[NCLS];
    float mx = neg_inf();
    #pragma unroll
    for (int c = 0; c < NCLS; c++) {
        sc[c] = g_ls[r * 55 + 44 + c];
        mx = fmaxf(mx, sc[c]);
    }
    float sum = 0.0f;
    #pragma unroll
    for (int c = 0; c < NCLS; c++) { sc[c] = expf(sc[c] - mx); sum += sc[c]; }
    #pragma unroll
    for (int c = 0; c < NCLS; c++) {
        float p = sc[c] / sum;
        g_prob[r * 11 + c] = p;
        out[NROI * 44 + r * 11 + c] = p;
    }
}

// ---------------- 5. per-class NMS ------------------------------------------
__global__ void __launch_bounds__(512) nms_kernel(float* __restrict__ out) {
    int cls = blockIdx.x + 1;
    int j = threadIdx.x;
    __shared__ float key[NROI];
    __shared__ int order[NROI];
    __shared__ float4 sb[NROI];
    __shared__ unsigned char keep[NROI];

    float s = g_prob[j * 11 + cls];
    bool valid = s > 0.05f;
    float kj = valid ? -s : pos_inf();
    key[j] = kj;
    __syncthreads();
    int rank = 0;
    for (int i = 0; i < NROI; i++) {
        float ki = key[i];
        rank += (ki < kj) || (ki == kj && i < j);
    }
    order[rank] = j;
    __syncthreads();
    int src = order[j];
    float4 box = *(const float4*)&g_bbox[src * 44 + cls * 4];
    sb[j] = box;
    keep[j] = (g_prob[src * 11 + cls] > 0.05f) ? 1 : 0;
    __syncthreads();

    float areaJ = (box.z - box.x) * (box.w - box.y);
    for (int i = 0; i < NROI - 1; i++) {
        if (keep[i] && j > i && keep[j]) {
            float4 bi = sb[i];
            float ty_ = fmaxf(box.x, bi.x);
            float tx_ = fmaxf(box.y, bi.y);
            float by_ = fminf(box.z, bi.z);
            float bx_ = fminf(box.w, bi.w);
            float ih = fmaxf(by_ - ty_, 0.0f);
            float iw = fmaxf(bx_ - tx_, 0.0f);
            float inter = ih * iw;
            float areaI = (bi.z - bi.x) * (bi.w - bi.y);
            float iou = inter / (areaJ + areaI - inter);
            if (iou > 0.3f) keep[j] = 0;
        }
        __syncthreads();
    }
    out[NROI * 44 + NROI * 11 + blockIdx.x * NROI + src] = keep[j] ? 1.0f : 0.0f;
}

// ---------------- launch ----------------------------------------------------
extern "C" void kernel_launch(void* const* d_in, const int* in_sizes, int n_in,
                              void* d_out, int out_size) {
    (void)in_sizes; (void)n_in; (void)out_size;
    const float* h    = (const float*)d_in[0];
    const float* rois = (const float*)d_in[1];
    const int*   ridx = (const int*)d_in[2];
    const float* W1   = (const float*)d_in[3];
    const float* b1   = (const float*)d_in[4];
    const float* W2   = (const float*)d_in[5];
    const float* b2   = (const float*)d_in[6];
    const float* Wloc = (const float*)d_in[7];
    const float* bloc = (const float*)d_in[8];
    const float* Wsc  = (const float*)d_in[9];
    const float* bsc  = (const float*)d_in[10];
    float* out = (float*)d_out;

    void *p_ph, *p_pl, *p_w1h, *p_w1l, *p_w2h, *p_w2l, *p_f1h, *p_f1l, *p_f7, *p_part;
    cudaGetSymbolAddress(&p_ph, g_poolh);
    cudaGetSymbolAddress(&p_pl, g_pooll);
    cudaGetSymbolAddress(&p_w1h, g_W1h);
    cudaGetSymbolAddress(&p_w1l, g_W1l);
    cudaGetSymbolAddress(&p_w2h, g_W2h);
    cudaGetSymbolAddress(&p_w2l, g_W2l);
    cudaGetSymbolAddress(&p_f1h, g_fc1h);
    cudaGetSymbolAddress(&p_f1l, g_fc1l);
    cudaGetSymbolAddress(&p_f7, g_fc7);
    cudaGetSymbolAddress(&p_part, g_part);

    cudaFuncSetAttribute(mma_fc_kernel,
                         cudaFuncAttributeMaxDynamicSharedMemorySize, GEMM_SMEM);

    const int total = NROI * FCDIM;            // 2M elements
    const int redBlocks = total / 4 / 256;     // 2048

    // ---- fork: splits on side streams, roipool on default ----
    cudaEventRecord(g_sp.ev0, 0);
    cudaStreamWaitEvent(g_sp.s1, g_sp.ev0, 0);
    cudaStreamWaitEvent(g_sp.s2, g_sp.ev0, 0);

    split_kernel<<<4096, 256, 0, g_sp.s1>>>(W1, (__nv_bfloat16*)p_w1h,       // 0
        (__nv_bfloat16*)p_w1l, (size_t)POOLDIM * FCDIM / 4);
    split_kernel<<<2048, 256, 0, g_sp.s2>>>(W2, (__nv_bfloat16*)p_w2h,       // 1
        (__nv_bfloat16*)p_w2l, (size_t)FCDIM * FCDIM / 4);
    roipool_kernel<<<NROI, 512>>>(h, rois, ridx);                            // 2

    cudaEventRecord(g_sp.ev1, g_sp.s1);
    cudaEventRecord(g_sp.ev2, g_sp.s2);
    cudaStreamWaitEvent(0, g_sp.ev1, 0);
    cudaStreamWaitEvent(0, g_sp.ev2, 0);

    // ---- joined: GEMMs on default stream ----
    dim3 grid(FCDIM / 128, NROI / 128, NSPLIT);   // (32, 4, 8) = 1024 CTAs
    mma_fc_kernel<<<grid, GEMM_THREADS, GEMM_SMEM>>>(                        // 3 (profiled)
        (const __nv_bfloat16*)p_ph, (const __nv_bfloat16*)p_pl,
        (const __nv_bfloat16*)p_w1h, (const __nv_bfloat16*)p_w1l,
        (float*)p_part, FCDIM, POOLDIM, POOLDIM / NSPLIT);

    // prep_head runs concurrently with GEMM1 on s2 (independent of it)
    prep_head_kernel<<<256, 256, 0, g_sp.s2>>>(Wloc, Wsc);                   // 4
    cudaEventRecord(g_sp.ev3, g_sp.s2);

    reduce_kernel<1><<<redBlocks, 256>>>(                                    // 5
        (const float*)p_part, b1, nullptr,
        (__nv_bfloat16*)p_f1h, (__nv_bfloat16*)p_f1l, FCDIM, total);
    mma_fc_kernel<<<grid, GEMM_THREADS, GEMM_SMEM>>>(                        // 6
        (const __nv_bfloat16*)p_f1h, (const __nv_bfloat16*)p_f1l,
        (const __nv_bfloat16*)p_w2h, (const __nv_bfloat16*)p_w2l,
        (float*)p_part, FCDIM, FCDIM, FCDIM / NSPLIT);
    reduce_kernel<0><<<redBlocks, 256>>>(                                    // 7
        (const float*)p_part, b2, (float*)p_f7, nullptr, nullptr, FCDIM, total);

    cudaStreamWaitEvent(0, g_sp.ev3, 0);
    head_kernel<<<NROI / 2, 256>>>(bloc, bsc);                               // 8
    post_kernel<<<(NROI + 255) / 256, 256>>>(rois, out);                     // 9
    nms_kernel<<<10, NROI>>>(out);                                           // 10
}

// round 13
// speedup vs baseline: 1.0028x; 1.0028x over previous
#include <cuda_runtime.h>
#include <cuda_bf16.h>
#include <math.h>
#include <stdint.h>

#define NROI 512
#define NCH 512
#define HF 37
#define WF 50
#define NCLS 11
#define POOLDIM 25088   // NCH * 7 * 7
#define FCDIM 4096
#define NSPLIT 8

// ---------------- scratch (device globals; no allocation allowed) ----------
__device__ __nv_bfloat16 g_poolh[(size_t)NROI * POOLDIM];
__device__ __nv_bfloat16 g_pooll[(size_t)NROI * POOLDIM];
__device__ __nv_bfloat16 g_W1h[(size_t)POOLDIM * FCDIM];
__device__ __nv_bfloat16 g_W1l[(size_t)POOLDIM * FCDIM];
__device__ __nv_bfloat16 g_W2h[(size_t)FCDIM * FCDIM];
__device__ __nv_bfloat16 g_W2l[(size_t)FCDIM * FCDIM];
__device__ __nv_bfloat16 g_fc1h[(size_t)NROI * FCDIM];
__device__ __nv_bfloat16 g_fc1l[(size_t)NROI * FCDIM];
__device__ float g_part[(size_t)NSPLIT * NROI * FCDIM];   // split-K partials (64MB)
__device__ float g_fc7[(size_t)NROI * FCDIM];
__device__ float g_Wt[55 * FCDIM];
__device__ float g_ls[NROI * 55];
__device__ float g_bbox[NROI * 44];
__device__ float g_prob[NROI * 11];

__device__ __forceinline__ float neg_inf() { return __int_as_float(0xff800000); }
__device__ __forceinline__ float pos_inf() { return __int_as_float(0x7f800000); }

// ---------------- streams/events, created once at static init --------------
struct StreamPack {
    cudaStream_t s1, s2;
    cudaEvent_t ev0, ev1, ev2, ev3;
    StreamPack() {
        cudaStreamCreateWithFlags(&s1, cudaStreamNonBlocking);
        cudaStreamCreateWithFlags(&s2, cudaStreamNonBlocking);
        cudaEventCreateWithFlags(&ev0, cudaEventDisableTiming);
        cudaEventCreateWithFlags(&ev1, cudaEventDisableTiming);
        cudaEventCreateWithFlags(&ev2, cudaEventDisableTiming);
        cudaEventCreateWithFlags(&ev3, cudaEventDisableTiming);
    }
};
static StreamPack g_sp;

// ========================= PTX helpers (baseline ISA only) =================
__device__ __forceinline__ uint32_t smem_u32(const void* p) {
    uint32_t a;
    asm("{ .reg .u64 t; cvta.to.shared.u64 t, %1; cvt.u32.u64 %0, t; }" : "=r"(a) : "l"(p));
    return a;
}
__device__ __forceinline__ uint32_t pack_bf16x2(float lo, float hi) {
    uint32_t r;
    asm("cvt.rn.bf16x2.f32 %0, %1, %2;" : "=r"(r) : "f"(hi), "f"(lo));
    return r;
}

#define LDM_X4(r, a) \
    asm volatile("ldmatrix.sync.aligned.m8n8.x4.shared.b16 {%0,%1,%2,%3}, [%4];" \
        : "=r"((r)[0]), "=r"((r)[1]), "=r"((r)[2]), "=r"((r)[3]) : "r"(a))
#define LDM_X4T(r, a) \
    asm volatile("ldmatrix.sync.aligned.m8n8.x4.trans.shared.b16 {%0,%1,%2,%3}, [%4];" \
        : "=r"((r)[0]), "=r"((r)[1]), "=r"((r)[2]), "=r"((r)[3]) : "r"(a))

__device__ __forceinline__ void mma16816(float* c, const uint32_t* a, uint32_t b0, uint32_t b1) {
    asm volatile(
        "mma.sync.aligned.m16n8k16.row.col.f32.bf16.bf16.f32 "
        "{%0,%1,%2,%3}, {%4,%5,%6,%7}, {%8,%9}, {%0,%1,%2,%3};"
        : "+f"(c[0]), "+f"(c[1]), "+f"(c[2]), "+f"(c[3])
        : "r"(a[0]), "r"(a[1]), "r"(a[2]), "r"(a[3]), "r"(b0), "r"(b1));
}

#define CP16(dst, src) \
    asm volatile("cp.async.cg.shared.global [%0], [%1], 16;" :: "r"(dst), "l"(src))
#define CP_COMMIT() asm volatile("cp.async.commit_group;" ::: "memory")
#define CP_WAIT0() asm volatile("cp.async.wait_group 0;" ::: "memory")
#define CP_WAIT1() asm volatile("cp.async.wait_group 1;" ::: "memory")
#define CP_WAIT2() asm volatile("cp.async.wait_group 2;" ::: "memory")

// ========================= split-bf16 HMMA GEMM (R7/R11 core + split-K) ====
// Partial[z] = A[:, zKs:(z+1)Ks] * B[zKs:(z+1)Ks, :]; 3-pass hh+hl+lh.
// Tile 128x128x32, 512 threads (16 warps, warp tile 32x32), 4-stage cp.async.
#define ST_AHI 0
#define ST_ALO 8192
#define ST_BHI 16384
#define ST_BLO 24576
#define STAGE_SZ 32768
#define NSTAGE 4
#define GEMM_SMEM (NSTAGE * STAGE_SZ)
#define GEMM_THREADS 512

__device__ __forceinline__ uint32_t aoff(int m, int k) {
    return (uint32_t)(m * 64 + ((((k >> 3) ^ ((m >> 1) ^ (m >> 3))) & 3) << 4) + (k & 7) * 2);
}
__device__ __forceinline__ uint32_t boff(int k, int n) {
    return (uint32_t)(k * 256 + ((((n >> 3) ^ (k & 7)) & 15) << 4) + (n & 7) * 2);
}

__global__ void __launch_bounds__(GEMM_THREADS, 1)
mma_fc_kernel(const __nv_bfloat16* __restrict__ Ah, const __nv_bfloat16* __restrict__ Al,
              const __nv_bfloat16* __restrict__ Bh, const __nv_bfloat16* __restrict__ Bl,
              float* __restrict__ Cpart, int N, int Ktot, int Ks) {
    extern __shared__ char smem[];
    uint32_t sbase = smem_u32(smem);
    const int t = threadIdx.x;
    const int lane = t & 31;
    const int wid = t >> 5;
    const int wy = wid & 3;
    const int wx = wid >> 2;
    const int m0 = blockIdx.y * 128;
    const int n0 = blockIdx.x * 128;
    const int kbase = blockIdx.z * Ks;

    const int am = t >> 2;
    const int ak = (t & 3) * 8;
    const int bk = t >> 4;
    const int bn = (t & 15) * 8;

    const uint32_t oA = ST_AHI + aoff(am, ak);
    const uint32_t oB = ST_BHI + boff(bk, bn);

    const int nit = Ks / 32;

    float acc[2][4][4];
    #pragma unroll
    for (int i = 0; i < 2; i++)
        #pragma unroll
        for (int j = 0; j < 4; j++)
            #pragma unroll
            for (int e = 0; e < 4; e++) acc[i][j][e] = 0.0f;

#define ISSUE(stg, kg) do {                                                    \
        uint32_t s_ = sbase + (uint32_t)(stg) * STAGE_SZ;                      \
        const __nv_bfloat16* ah_ = Ah + (size_t)(m0 + am) * Ktot + (kg) + ak;  \
        const __nv_bfloat16* al_ = Al + (size_t)(m0 + am) * Ktot + (kg) + ak;  \
        CP16(s_ + oA, ah_);                                                    \
        CP16(s_ + oA + (ST_ALO - ST_AHI), al_);                                \
        const __nv_bfloat16* bh_ = Bh + (size_t)((kg) + bk) * N + n0 + bn;     \
        const __nv_bfloat16* bl_ = Bl + (size_t)((kg) + bk) * N + n0 + bn;     \
        CP16(s_ + oB, bh_);                                                    \
        CP16(s_ + oB + (ST_BLO - ST_BHI), bl_);                                \
        CP_COMMIT();                                                           \
    } while (0)

    ISSUE(0, kbase);
    ISSUE(1, kbase + 32);
    ISSUE(2, kbase + 64);

    const int arow_l = lane & 15;
    const int khalf = (lane >> 4) << 3;

    int cur = 0, nxt = 3;
    for (int it = 0; it < nit; it++) {
        if (it < nit - 2)      { CP_WAIT2(); }
        else if (it == nit - 2){ CP_WAIT1(); }
        else                   { CP_WAIT0(); }
        __syncthreads();
        if (it + 3 < nit) {
            ISSUE(nxt, kbase + (it + 3) * 32);
            if (++nxt == NSTAGE) nxt = 0;
        }

        uint32_t sA_hi = sbase + (uint32_t)cur * STAGE_SZ + ST_AHI;
        uint32_t sA_lo = sA_hi + (ST_ALO - ST_AHI);
        uint32_t sB_hi = sbase + (uint32_t)cur * STAGE_SZ + ST_BHI;
        uint32_t sB_lo = sB_hi + (ST_BLO - ST_BHI);
        if (++cur == NSTAGE) cur = 0;

        #pragma unroll
        for (int ks = 0; ks < 2; ks++) {
            const int k0 = ks * 16;
            uint32_t ah[2][4], al[2][4], bh[2][4], bl[2][4];
            #pragma unroll
            for (int mi = 0; mi < 2; mi++) {
                int mrow = wy * 32 + mi * 16 + arow_l;
                uint32_t oa = aoff(mrow, k0 + khalf);
                LDM_X4(ah[mi], sA_hi + oa);
                LDM_X4(al[mi], sA_lo + oa);
            }
            #pragma unroll
            for (int nt = 0; nt < 2; nt++) {
                int krow = k0 + (lane & 15);
                int ncol = wx * 32 + nt * 16 + khalf;
                uint32_t ob = boff(krow, ncol);
                LDM_X4T(bh[nt], sB_hi + ob);
                LDM_X4T(bl[nt], sB_lo + ob);
            }
            // pass-major: RAW distance between same-acc MMAs is 8
            #pragma unroll
            for (int mi = 0; mi < 2; mi++)
                #pragma unroll
                for (int ni = 0; ni < 4; ni++)
                    mma16816(acc[mi][ni], ah[mi], bh[ni >> 1][(ni & 1) * 2],
                             bh[ni >> 1][(ni & 1) * 2 + 1]);
            #pragma unroll
            for (int mi = 0; mi < 2; mi++)
                #pragma unroll
                for (int ni = 0; ni < 4; ni++)
                    mma16816(acc[mi][ni], ah[mi], bl[ni >> 1][(ni & 1) * 2],
                             bl[ni >> 1][(ni & 1) * 2 + 1]);
            #pragma unroll
            for (int mi = 0; mi < 2; mi++)
                #pragma unroll
                for (int ni = 0; ni < 4; ni++)
                    mma16816(acc[mi][ni], al[mi], bh[ni >> 1][(ni & 1) * 2],
                             bh[ni >> 1][(ni & 1) * 2 + 1]);
        }
    }

    // ---- epilogue: raw fp32 partial store ----
    float* Cp = Cpart + (size_t)blockIdx.z * (size_t)(gridDim.y * 128) * N;
    #pragma unroll
    for (int mi = 0; mi < 2; mi++) {
        int mrow = m0 + wy * 32 + mi * 16 + (lane >> 2);
        #pragma unroll
        for (int ni = 0; ni < 4; ni++) {
            int ncol = n0 + wx * 32 + ni * 8 + (lane & 3) * 2;
            *(float2*)(Cp + (size_t)mrow * N + ncol) =
                make_float2(acc[mi][ni][0], acc[mi][ni][1]);
            *(float2*)(Cp + (size_t)(mrow + 8) * N + ncol) =
                make_float2(acc[mi][ni][2], acc[mi][ni][3]);
        }
    }
#undef ISSUE
}

// ---------------- split-K reduce: sum partials + bias + relu ---------------
template <int OUT>
__global__ void __launch_bounds__(256) reduce_kernel(
        const float* __restrict__ part, const float* __restrict__ bias,
        float* __restrict__ Cf, __nv_bfloat16* __restrict__ Ch,
        __nv_bfloat16* __restrict__ Cl, int N, int total) {
    int i4 = blockIdx.x * blockDim.x + threadIdx.x;   // float4 index
    if (i4 * 4 >= total) return;
    float4 s = ((const float4*)part)[i4];
    #pragma unroll
    for (int z = 1; z < NSPLIT; z++) {
        float4 p = ((const float4*)(part + (size_t)z * total))[i4];
        s.x += p.x; s.y += p.y; s.z += p.z; s.w += p.w;
    }
    int e = i4 * 4;
    int n = e & (N - 1);
    s.x = fmaxf(s.x + bias[n],     0.0f);
    s.y = fmaxf(s.y + bias[n + 1], 0.0f);
    s.z = fmaxf(s.z + bias[n + 2], 0.0f);
    s.w = fmaxf(s.w + bias[n + 3], 0.0f);
    if (OUT == 0) {
        ((float4*)Cf)[i4] = s;
    } else {
        uint32_t h01 = pack_bf16x2(s.x, s.y);
        uint32_t h23 = pack_bf16x2(s.z, s.w);
        uint32_t l01 = pack_bf16x2(s.x - __uint_as_float(h01 << 16),
                                   s.y - __uint_as_float(h01 & 0xffff0000u));
        uint32_t l23 = pack_bf16x2(s.z - __uint_as_float(h23 << 16),
                                   s.w - __uint_as_float(h23 & 0xffff0000u));
        ((uint2*)Ch)[i4] = make_uint2(h01, h23);
        ((uint2*)Cl)[i4] = make_uint2(l01, l23);
    }
}

// ---------------- 0. fp32 -> bf16 hi/lo split (streaming) -------------------
__global__ void split_kernel(const float* __restrict__ src,
                             __nv_bfloat16* __restrict__ hi,
                             __nv_bfloat16* __restrict__ lo, size_t n4) {
    size_t stride = (size_t)gridDim.x * blockDim.x;
    for (size_t i = (size_t)blockIdx.x * blockDim.x + threadIdx.x; i < n4; i += stride) {
        float4 v = ((const float4*)src)[i];
        uint32_t h0 = pack_bf16x2(v.x, v.y);
        uint32_t h1 = pack_bf16x2(v.z, v.w);
        uint32_t l0 = pack_bf16x2(v.x - __uint_as_float(h0 << 16),
                                  v.y - __uint_as_float(h0 & 0xffff0000u));
        uint32_t l1 = pack_bf16x2(v.z - __uint_as_float(h1 << 16),
                                  v.w - __uint_as_float(h1 & 0xffff0000u));
        ((uint2*)hi)[i] = make_uint2(h0, h1);
        ((uint2*)lo)[i] = make_uint2(l0, l1);
    }
}

// ---------------- 1. ROI max-pool (emits bf16 hi/lo directly) ---------------
__global__ void __launch_bounds__(512) roipool_kernel(const float* __restrict__ feat,
                               const float* __restrict__ rois,
                               const int* __restrict__ roi_idx) {
    int r = blockIdx.x;
    __shared__ int hs[7], he[7], ws[7], we[7];
    if (threadIdx.x == 0) {
        const float RECIP7 = 1.0f / 7.0f;   // matches XLA's x/7 -> x*recip rewrite
        float y1 = rois[r * 4 + 0], x1 = rois[r * 4 + 1];
        float y2 = rois[r * 4 + 2], x2 = rois[r * 4 + 3];
        float sw = rintf(x1 * 0.0625f);
        float ew = rintf(x2 * 0.0625f);
        float sh = rintf(y1 * 0.0625f);
        float eh = rintf(y2 * 0.0625f);
        float rw = fmaxf(ew - sw + 1.0f, 1.0f);
        float rh = fmaxf(eh - sh + 1.0f, 1.0f);
        #pragma unroll
        for (int p = 0; p < 7; p++) {
            float fp = (float)p;
            float h0 = floorf(__fmul_rn(fp * rh, RECIP7)) + sh;
            float h1 = ceilf(__fmul_rn((fp + 1.0f) * rh, RECIP7)) + sh;
            float w0 = floorf(__fmul_rn(fp * rw, RECIP7)) + sw;
            float w1 = ceilf(__fmul_rn((fp + 1.0f) * rw, RECIP7)) + sw;
            hs[p] = (int)fminf(fmaxf(h0, 0.0f), (float)HF);
            he[p] = (int)fminf(fmaxf(h1, 0.0f), (float)HF);
            ws[p] = (int)fminf(fmaxf(w0, 0.0f), (float)WF);
            we[p] = (int)fminf(fmaxf(w1, 0.0f), (float)WF);
        }
    }
    __syncthreads();
    int b = roi_idx[r];
    const float* f = feat + (size_t)b * NCH * HF * WF;
    for (int idx = threadIdx.x; idx < POOLDIM; idx += blockDim.x) {
        int c = idx / 49;
        int rem = idx - c * 49;
        int ph = rem / 7, pw = rem - (rem / 7) * 7;
        int h0 = hs[ph], h1 = he[ph], w0 = ws[pw], w1 = we[pw];
        float m = 0.0f;
        if (h1 > h0 && w1 > w0) {
            m = neg_inf();
            const float* fc_ = f + (size_t)c * (HF * WF);
            for (int y = h0; y < h1; y++)
                for (int x = w0; x < w1; x++)
                    m = fmaxf(m, fc_[y * WF + x]);
        }
        __nv_bfloat16 hb = __float2bfloat16(m);
        g_poolh[(size_t)r * POOLDIM + idx] = hb;
        g_pooll[(size_t)r * POOLDIM + idx] = __float2bfloat16(m - __bfloat162float(hb));
    }
}

// ---------------- 2. head W transpose: g_Wt[55][4096] ----------------------
__global__ void prep_head_kernel(const float* __restrict__ Wloc,
                                 const float* __restrict__ Wsc) {
    int stride = gridDim.x * blockDim.x;
    for (int i = blockIdx.x * blockDim.x + threadIdx.x; i < 55 * FCDIM; i += stride) {
        int col = i >> 12;
        int k = i & (FCDIM - 1);
        g_Wt[i] = (col < 44) ? Wloc[(size_t)k * 44 + col] : Wsc[(size_t)k * 11 + (col - 44)];
    }
}

// ---------------- 3. heads: 2 ROIs per block, warp-per-output --------------
__global__ void __launch_bounds__(256) head_kernel(const float* __restrict__ bloc,
                                                   const float* __restrict__ bsc) {
    __shared__ float4 Fs[2][FCDIM / 4];
    int r0 = blockIdx.x * 2;
    int t = threadIdx.x;
    for (int i = t; i < 2 * (FCDIM / 4); i += 256) {
        int ri = i >> 10, kk = i & 1023;
        Fs[ri][kk] = ((const float4*)g_fc7)[(size_t)(r0 + ri) * (FCDIM / 4) + kk];
    }
    __syncthreads();
    int w = t >> 5, lane = t & 31;
    for (int o = w; o < 110; o += 8) {
        int roi = (o >= 55) ? 1 : 0;
        int col = o - roi * 55;
        const float4* wp = (const float4*)(g_Wt + col * FCDIM);
        float acc = 0.0f;
        for (int kb = lane; kb < FCDIM / 4; kb += 32) {
            float4 f = Fs[roi][kb];
            float4 v = wp[kb];
            acc = fmaf(f.x, v.x, acc);
            acc = fmaf(f.y, v.y, acc);
            acc = fmaf(f.z, v.z, acc);
            acc = fmaf(f.w, v.w, acc);
        }
        #pragma unroll
        for (int of = 16; of > 0; of >>= 1) acc += __shfl_xor_sync(0xffffffffu, acc, of);
        if (lane == 0) {
            float bb = (col < 44) ? bloc[col] : bsc[col - 44];
            g_ls[(r0 + roi) * 55 + col] = acc + bb;
        }
    }
}

// ---------------- 4. bbox decode + clip + softmax ---------------------------
__global__ void post_kernel(const float* __restrict__ rois, float* __restrict__ out) {
    int r = blockIdx.x * blockDim.x + threadIdx.x;
    if (r >= NROI) return;
    float y1 = rois[r * 4 + 0], x1 = rois[r * 4 + 1];
    float y2 = rois[r * 4 + 2], x2 = rois[r * 4 + 3];
    float sh_ = y2 - y1, sw_ = x2 - x1;
    float cy = y1 + 0.5f * sh_, cx = x1 + 0.5f * sw_;
    #pragma unroll
    for (int c = 0; c < NCLS; c++) {
        float dy = g_ls[r * 55 + c * 4 + 0] * 0.1f;
        float dx = g_ls[r * 55 + c * 4 + 1] * 0.1f;
        float dh = g_ls[r * 55 + c * 4 + 2] * 0.2f;
        float dw = g_ls[r * 55 + c * 4 + 3] * 0.2f;
        float ncy = dy * sh_ + cy;
        float ncx = dx * sw_ + cx;
        float nh = expf(dh) * sh_;
        float nw = expf(dw) * sw_;
        float by1 = fminf(fmaxf(ncy - 0.5f * nh, 0.0f), 600.0f);
        float bx1 = fminf(fmaxf(ncx - 0.5f * nw, 0.0f), 800.0f);
        float by2 = fminf(fmaxf(ncy + 0.5f * nh, 0.0f), 600.0f);
        float bx2 = fminf(fmaxf(ncx + 0.5f * nw, 0.0f), 800.0f);
        g_bbox[r * 44 + c * 4 + 0] = by1;
        g_bbox[r * 44 + c * 4 + 1] = bx1;
        g_bbox[r * 44 + c * 4 + 2] = by2;
        g_bbox[r * 44 + c * 4 + 3] = bx2;
        out[r * 44 + c * 4 + 0] = by1;
        out[r * 44 + c * 4 + 1] = bx1;
        out[r * 44 + c * 4 + 2] = by2;
        out[r * 44 + c * 4 + 3] = bx2;
    }
    float sc[NCLS];
    float mx = neg_inf();
    #pragma unroll
    for (int c = 0; c < NCLS; c++) {
        sc[c] = g_ls[r * 55 + 44 + c];
        mx = fmaxf(mx, sc[c]);
    }
    float sum = 0.0f;
    #pragma unroll
    for (int c = 0; c < NCLS; c++) { sc[c] = expf(sc[c] - mx); sum += sc[c]; }
    #pragma unroll
    for (int c = 0; c < NCLS; c++) {
        float p = sc[c] / sum;
        g_prob[r * 11 + c] = p;
        out[NROI * 44 + r * 11 + c] = p;
    }
}

// ---------------- 5. per-class NMS ------------------------------------------
__global__ void __launch_bounds__(512) nms_kernel(float* __restrict__ out) {
    int cls = blockIdx.x + 1;
    int j = threadIdx.x;
    __shared__ float key[NROI];
    __shared__ int order[NROI];
    __shared__ float4 sb[NROI];
    __shared__ unsigned char keep[NROI];

    float s = g_prob[j * 11 + cls];
    bool valid = s > 0.05f;
    float kj = valid ? -s : pos_inf();
    key[j] = kj;
    __syncthreads();
    int rank = 0;
    for (int i = 0; i < NROI; i++) {
        float ki = key[i];
        rank += (ki < kj) || (ki == kj && i < j);
    }
    order[rank] = j;
    __syncthreads();
    int src = order[j];
    float4 box = *(const float4*)&g_bbox[src * 44 + cls * 4];
    sb[j] = box;
    keep[j] = (g_prob[src * 11 + cls] > 0.05f) ? 1 : 0;
    __syncthreads();

    float areaJ = (box.z - box.x) * (box.w - box.y);
    for (int i = 0; i < NROI - 1; i++) {
        if (keep[i] && j > i && keep[j]) {
            float4 bi = sb[i];
            float ty_ = fmaxf(box.x, bi.x);
            float tx_ = fmaxf(box.y, bi.y);
            float by_ = fminf(box.z, bi.z);
            float bx_ = fminf(box.w, bi.w);
            float ih = fmaxf(by_ - ty_, 0.0f);
            float iw = fmaxf(bx_ - tx_, 0.0f);
            float inter = ih * iw;
            float areaI = (bi.z - bi.x) * (bi.w - bi.y);
            float iou = inter / (areaJ + areaI - inter);
            if (iou > 0.3f) keep[j] = 0;
        }
        __syncthreads();
    }
    out[NROI * 44 + NROI * 11 + blockIdx.x * NROI + src] = keep[j] ? 1.0f : 0.0f;
}

// ---------------- launch ----------------------------------------------------
extern "C" void kernel_launch(void* const* d_in, const int* in_sizes, int n_in,
                              void* d_out, int out_size) {
    (void)in_sizes; (void)n_in; (void)out_size;
    const float* h    = (const float*)d_in[0];
    const float* rois = (const float*)d_in[1];
    const int*   ridx = (const int*)d_in[2];
    const float* W1   = (const float*)d_in[3];
    const float* b1   = (const float*)d_in[4];
    const float* W2   = (const float*)d_in[5];
    const float* b2   = (const float*)d_in[6];
    const float* Wloc = (const float*)d_in[7];
    const float* bloc = (const float*)d_in[8];
    const float* Wsc  = (const float*)d_in[9];
    const float* bsc  = (const float*)d_in[10];
    float* out = (float*)d_out;

    void *p_ph, *p_pl, *p_w1h, *p_w1l, *p_w2h, *p_w2l, *p_f1h, *p_f1l, *p_f7, *p_part;
    cudaGetSymbolAddress(&p_ph, g_poolh);
    cudaGetSymbolAddress(&p_pl, g_pooll);
    cudaGetSymbolAddress(&p_w1h, g_W1h);
    cudaGetSymbolAddress(&p_w1l, g_W1l);
    cudaGetSymbolAddress(&p_w2h, g_W2h);
    cudaGetSymbolAddress(&p_w2l, g_W2l);
    cudaGetSymbolAddress(&p_f1h, g_fc1h);
    cudaGetSymbolAddress(&p_f1l, g_fc1l);
    cudaGetSymbolAddress(&p_f7, g_fc7);
    cudaGetSymbolAddress(&p_part, g_part);

    cudaFuncSetAttribute(mma_fc_kernel,
                         cudaFuncAttributeMaxDynamicSharedMemorySize, GEMM_SMEM);

    const int total = NROI * FCDIM;            // 2M elements
    const int redBlocks = total / 4 / 256;     // 2048

    // ---- fork ----
    cudaEventRecord(g_sp.ev0, 0);
    cudaStreamWaitEvent(g_sp.s1, g_sp.ev0, 0);
    cudaStreamWaitEvent(g_sp.s2, g_sp.ev0, 0);

    split_kernel<<<4096, 256, 0, g_sp.s1>>>(W1, (__nv_bfloat16*)p_w1h,       // 0
        (__nv_bfloat16*)p_w1l, (size_t)POOLDIM * FCDIM / 4);
    cudaEventRecord(g_sp.ev1, g_sp.s1);                 // W1 split done

    split_kernel<<<2048, 256, 0, g_sp.s2>>>(W2, (__nv_bfloat16*)p_w2h,       // 1
        (__nv_bfloat16*)p_w2l, (size_t)FCDIM * FCDIM / 4);
    cudaEventRecord(g_sp.ev2, g_sp.s2);                 // W2 split done (only GEMM2 needs it)

    roipool_kernel<<<NROI, 512>>>(h, rois, ridx);                            // 2

    // GEMM1 waits ONLY on split1 (+ roipool via stream order). split2 and
    // prep_head run in GEMM1's shadow on s2.
    cudaStreamWaitEvent(0, g_sp.ev1, 0);

    dim3 grid(FCDIM / 128, NROI / 128, NSPLIT);   // (32, 4, 8) = 1024 CTAs
    mma_fc_kernel<<<grid, GEMM_THREADS, GEMM_SMEM>>>(                        // 3 (profiled)
        (const __nv_bfloat16*)p_ph, (const __nv_bfloat16*)p_pl,
        (const __nv_bfloat16*)p_w1h, (const __nv_bfloat16*)p_w1l,
        (float*)p_part, FCDIM, POOLDIM, POOLDIM / NSPLIT);

    prep_head_kernel<<<256, 256, 0, g_sp.s2>>>(Wloc, Wsc);                   // 4 (on s2, after split2)
    cudaEventRecord(g_sp.ev3, g_sp.s2);

    reduce_kernel<1><<<redBlocks, 256>>>(                                    // 5
        (const float*)p_part, b1, nullptr,
        (__nv_bfloat16*)p_f1h, (__nv_bfloat16*)p_f1l, FCDIM, total);

    cudaStreamWaitEvent(0, g_sp.ev2, 0);                // need W2 split now
    mma_fc_kernel<<<grid, GEMM_THREADS, GEMM_SMEM>>>(                        // 6
        (const __nv_bfloat16*)p_f1h, (const __nv_bfloat16*)p_f1l,
        (const __nv_bfloat16*)p_w2h, (const __nv_bfloat16*)p_w2l,
        (float*)p_part, FCDIM, FCDIM, FCDIM / NSPLIT);
    reduce_kernel<0><<<redBlocks, 256>>>(                                    // 7
        (const float*)p_part, b2, (float*)p_f7, nullptr, nullptr, FCDIM, total);

    cudaStreamWaitEvent(0, g_sp.ev3, 0);
    head_kernel<<<NROI / 2, 256>>>(bloc, bsc);                               // 8
    post_kernel<<<(NROI + 255) / 256, 256>>>(rois, out);                     // 9
    nms_kernel<<<10, NROI>>>(out);                                           // 10
}

// round 14
// speedup vs baseline: 1.0229x; 1.0200x over previous
#include <cuda_runtime.h>
#include <cuda_bf16.h>
#include <math.h>
#include <stdint.h>

#define NROI 512
#define NCH 512
#define HF 37
#define WF 50
#define NCLS 11
#define POOLDIM 25088   // NCH * 7 * 7
#define FCDIM 4096
#define NSPLIT 8

// ---------------- scratch (device globals; no allocation allowed) ----------
__device__ __nv_bfloat16 g_poolh[(size_t)NROI * POOLDIM];
__device__ __nv_bfloat16 g_pooll[(size_t)NROI * POOLDIM];
__device__ __nv_bfloat16 g_W1h[(size_t)POOLDIM * FCDIM];
__device__ __nv_bfloat16 g_W1l[(size_t)POOLDIM * FCDIM];
__device__ __nv_bfloat16 g_W2h[(size_t)FCDIM * FCDIM];
__device__ __nv_bfloat16 g_W2l[(size_t)FCDIM * FCDIM];
__device__ __nv_bfloat16 g_fc1h[(size_t)NROI * FCDIM];
__device__ __nv_bfloat16 g_fc1l[(size_t)NROI * FCDIM];
__device__ float g_part[(size_t)NSPLIT * NROI * FCDIM];   // split-K partials (64MB)
__device__ float g_fc7[(size_t)NROI * FCDIM];
__device__ float g_Wt[55 * FCDIM];
__device__ float g_ls[NROI * 55];
__device__ float g_bbox[NROI * 44];
__device__ float g_prob[NROI * 11];

__device__ __forceinline__ float neg_inf() { return __int_as_float(0xff800000); }
__device__ __forceinline__ float pos_inf() { return __int_as_float(0x7f800000); }

// ---------------- streams/events, created once at static init --------------
struct StreamPack {
    cudaStream_t s1, s2;
    cudaEvent_t ev0, ev1, ev2, ev3;
    StreamPack() {
        cudaStreamCreateWithFlags(&s1, cudaStreamNonBlocking);
        cudaStreamCreateWithFlags(&s2, cudaStreamNonBlocking);
        cudaEventCreateWithFlags(&ev0, cudaEventDisableTiming);
        cudaEventCreateWithFlags(&ev1, cudaEventDisableTiming);
        cudaEventCreateWithFlags(&ev2, cudaEventDisableTiming);
        cudaEventCreateWithFlags(&ev3, cudaEventDisableTiming);
    }
};
static StreamPack g_sp;

// ========================= PTX helpers (baseline ISA only) =================
__device__ __forceinline__ uint32_t smem_u32(const void* p) {
    uint32_t a;
    asm("{ .reg .u64 t; cvta.to.shared.u64 t, %1; cvt.u32.u64 %0, t; }" : "=r"(a) : "l"(p));
    return a;
}
__device__ __forceinline__ uint32_t pack_bf16x2(float lo, float hi) {
    uint32_t r;
    asm("cvt.rn.bf16x2.f32 %0, %1, %2;" : "=r"(r) : "f"(hi), "f"(lo));
    return r;
}

#define LDM_X4(r, a) \
    asm volatile("ldmatrix.sync.aligned.m8n8.x4.shared.b16 {%0,%1,%2,%3}, [%4];" \
        : "=r"((r)[0]), "=r"((r)[1]), "=r"((r)[2]), "=r"((r)[3]) : "r"(a))
#define LDM_X4T(r, a) \
    asm volatile("ldmatrix.sync.aligned.m8n8.x4.trans.shared.b16 {%0,%1,%2,%3}, [%4];" \
        : "=r"((r)[0]), "=r"((r)[1]), "=r"((r)[2]), "=r"((r)[3]) : "r"(a))

__device__ __forceinline__ void mma16816(float* c, const uint32_t* a, uint32_t b0, uint32_t b1) {
    asm volatile(
        "mma.sync.aligned.m16n8k16.row.col.f32.bf16.bf16.f32 "
        "{%0,%1,%2,%3}, {%4,%5,%6,%7}, {%8,%9}, {%0,%1,%2,%3};"
        : "+f"(c[0]), "+f"(c[1]), "+f"(c[2]), "+f"(c[3])
        : "r"(a[0]), "r"(a[1]), "r"(a[2]), "r"(a[3]), "r"(b0), "r"(b1));
}

#define CP16(dst, src) \
    asm volatile("cp.async.cg.shared.global [%0], [%1], 16;" :: "r"(dst), "l"(src))
#define CP_COMMIT() asm volatile("cp.async.commit_group;" ::: "memory")
#define CP_WAIT0() asm volatile("cp.async.wait_group 0;" ::: "memory")
#define CP_WAIT1() asm volatile("cp.async.wait_group 1;" ::: "memory")
#define CP_WAIT2() asm volatile("cp.async.wait_group 2;" ::: "memory")

// ========================= split-bf16 HMMA GEMM (R7/R11 core + split-K) ====
// Partial[z] = A[:, zKs:(z+1)Ks] * B[zKs:(z+1)Ks, :]; 3-pass hh+hl+lh.
// Tile 128x128x32, 512 threads (16 warps, warp tile 32x32), 4-stage cp.async.
#define ST_AHI 0
#define ST_ALO 8192
#define ST_BHI 16384
#define ST_BLO 24576
#define STAGE_SZ 32768
#define NSTAGE 4
#define GEMM_SMEM (NSTAGE * STAGE_SZ)
#define GEMM_THREADS 512

__device__ __forceinline__ uint32_t aoff(int m, int k) {
    return (uint32_t)(m * 64 + ((((k >> 3) ^ ((m >> 1) ^ (m >> 3))) & 3) << 4) + (k & 7) * 2);
}
__device__ __forceinline__ uint32_t boff(int k, int n) {
    return (uint32_t)(k * 256 + ((((n >> 3) ^ (k & 7)) & 15) << 4) + (n & 7) * 2);
}

__global__ void __launch_bounds__(GEMM_THREADS, 1)
mma_fc_kernel(const __nv_bfloat16* __restrict__ Ah, const __nv_bfloat16* __restrict__ Al,
              const __nv_bfloat16* __restrict__ Bh, const __nv_bfloat16* __restrict__ Bl,
              float* __restrict__ Cpart, int N, int Ktot, int Ks) {
    extern __shared__ char smem[];
    uint32_t sbase = smem_u32(smem);
    const int t = threadIdx.x;
    const int lane = t & 31;
    const int wid = t >> 5;
    const int wy = wid & 3;
    const int wx = wid >> 2;
    const int m0 = blockIdx.y * 128;
    const int n0 = blockIdx.x * 128;
    const int kbase = blockIdx.z * Ks;

    const int am = t >> 2;
    const int ak = (t & 3) * 8;
    const int bk = t >> 4;
    const int bn = (t & 15) * 8;

    const uint32_t oA = ST_AHI + aoff(am, ak);
    const uint32_t oB = ST_BHI + boff(bk, bn);

    const int nit = Ks / 32;

    float acc[2][4][4];
    #pragma unroll
    for (int i = 0; i < 2; i++)
        #pragma unroll
        for (int j = 0; j < 4; j++)
            #pragma unroll
            for (int e = 0; e < 4; e++) acc[i][j][e] = 0.0f;

#define ISSUE(stg, kg) do {                                                    \
        uint32_t s_ = sbase + (uint32_t)(stg) * STAGE_SZ;                      \
        const __nv_bfloat16* ah_ = Ah + (size_t)(m0 + am) * Ktot + (kg) + ak;  \
        const __nv_bfloat16* al_ = Al + (size_t)(m0 + am) * Ktot + (kg) + ak;  \
        CP16(s_ + oA, ah_);                                                    \
        CP16(s_ + oA + (ST_ALO - ST_AHI), al_);                                \
        const __nv_bfloat16* bh_ = Bh + (size_t)((kg) + bk) * N + n0 + bn;     \
        const __nv_bfloat16* bl_ = Bl + (size_t)((kg) + bk) * N + n0 + bn;     \
        CP16(s_ + oB, bh_);                                                    \
        CP16(s_ + oB + (ST_BLO - ST_BHI), bl_);                                \
        CP_COMMIT();                                                           \
    } while (0)

    ISSUE(0, kbase);
    ISSUE(1, kbase + 32);
    ISSUE(2, kbase + 64);

    const int arow_l = lane & 15;
    const int khalf = (lane >> 4) << 3;

    int cur = 0, nxt = 3;
    for (int it = 0; it < nit; it++) {
        if (it < nit - 2)      { CP_WAIT2(); }
        else if (it == nit - 2){ CP_WAIT1(); }
        else                   { CP_WAIT0(); }
        __syncthreads();
        if (it + 3 < nit) {
            ISSUE(nxt, kbase + (it + 3) * 32);
            if (++nxt == NSTAGE) nxt = 0;
        }

        uint32_t sA_hi = sbase + (uint32_t)cur * STAGE_SZ + ST_AHI;
        uint32_t sA_lo = sA_hi + (ST_ALO - ST_AHI);
        uint32_t sB_hi = sbase + (uint32_t)cur * STAGE_SZ + ST_BHI;
        uint32_t sB_lo = sB_hi + (ST_BLO - ST_BHI);
        if (++cur == NSTAGE) cur = 0;

        #pragma unroll
        for (int ks = 0; ks < 2; ks++) {
            const int k0 = ks * 16;
            uint32_t ah[2][4], al[2][4], bh[2][4], bl[2][4];
            #pragma unroll
            for (int mi = 0; mi < 2; mi++) {
                int mrow = wy * 32 + mi * 16 + arow_l;
                uint32_t oa = aoff(mrow, k0 + khalf);
                LDM_X4(ah[mi], sA_hi + oa);
                LDM_X4(al[mi], sA_lo + oa);
            }
            #pragma unroll
            for (int nt = 0; nt < 2; nt++) {
                int krow = k0 + (lane & 15);
                int ncol = wx * 32 + nt * 16 + khalf;
                uint32_t ob = boff(krow, ncol);
                LDM_X4T(bh[nt], sB_hi + ob);
                LDM_X4T(bl[nt], sB_lo + ob);
            }
            // pass-major: RAW distance between same-acc MMAs is 8
            #pragma unroll
            for (int mi = 0; mi < 2; mi++)
                #pragma unroll
                for (int ni = 0; ni < 4; ni++)
                    mma16816(acc[mi][ni], ah[mi], bh[ni >> 1][(ni & 1) * 2],
                             bh[ni >> 1][(ni & 1) * 2 + 1]);
            #pragma unroll
            for (int mi = 0; mi < 2; mi++)
                #pragma unroll
                for (int ni = 0; ni < 4; ni++)
                    mma16816(acc[mi][ni], ah[mi], bl[ni >> 1][(ni & 1) * 2],
                             bl[ni >> 1][(ni & 1) * 2 + 1]);
            #pragma unroll
            for (int mi = 0; mi < 2; mi++)
                #pragma unroll
                for (int ni = 0; ni < 4; ni++)
                    mma16816(acc[mi][ni], al[mi], bh[ni >> 1][(ni & 1) * 2],
                             bh[ni >> 1][(ni & 1) * 2 + 1]);
        }
    }

    // ---- epilogue: raw fp32 partial store ----
    float* Cp = Cpart + (size_t)blockIdx.z * (size_t)(gridDim.y * 128) * N;
    #pragma unroll
    for (int mi = 0; mi < 2; mi++) {
        int mrow = m0 + wy * 32 + mi * 16 + (lane >> 2);
        #pragma unroll
        for (int ni = 0; ni < 4; ni++) {
            int ncol = n0 + wx * 32 + ni * 8 + (lane & 3) * 2;
            *(float2*)(Cp + (size_t)mrow * N + ncol) =
                make_float2(acc[mi][ni][0], acc[mi][ni][1]);
            *(float2*)(Cp + (size_t)(mrow + 8) * N + ncol) =
                make_float2(acc[mi][ni][2], acc[mi][ni][3]);
        }
    }
#undef ISSUE
}

// ---------------- split-K reduce: sum partials + bias + relu ---------------
template <int OUT>
__global__ void __launch_bounds__(256) reduce_kernel(
        const float* __restrict__ part, const float* __restrict__ bias,
        float* __restrict__ Cf, __nv_bfloat16* __restrict__ Ch,
        __nv_bfloat16* __restrict__ Cl, int N, int total) {
    int i4 = blockIdx.x * blockDim.x + threadIdx.x;   // float4 index
    if (i4 * 4 >= total) return;
    float4 s = ((const float4*)part)[i4];
    #pragma unroll
    for (int z = 1; z < NSPLIT; z++) {
        float4 p = ((const float4*)(part + (size_t)z * total))[i4];
        s.x += p.x; s.y += p.y; s.z += p.z; s.w += p.w;
    }
    int e = i4 * 4;
    int n = e & (N - 1);
    s.x = fmaxf(s.x + bias[n],     0.0f);
    s.y = fmaxf(s.y + bias[n + 1], 0.0f);
    s.z = fmaxf(s.z + bias[n + 2], 0.0f);
    s.w = fmaxf(s.w + bias[n + 3], 0.0f);
    if (OUT == 0) {
        ((float4*)Cf)[i4] = s;
    } else {
        uint32_t h01 = pack_bf16x2(s.x, s.y);
        uint32_t h23 = pack_bf16x2(s.z, s.w);
        uint32_t l01 = pack_bf16x2(s.x - __uint_as_float(h01 << 16),
                                   s.y - __uint_as_float(h01 & 0xffff0000u));
        uint32_t l23 = pack_bf16x2(s.z - __uint_as_float(h23 << 16),
                                   s.w - __uint_as_float(h23 & 0xffff0000u));
        ((uint2*)Ch)[i4] = make_uint2(h01, h23);
        ((uint2*)Cl)[i4] = make_uint2(l01, l23);
    }
}

// ---------------- 0. fp32 -> bf16 hi/lo split (streaming) -------------------
__global__ void split_kernel(const float* __restrict__ src,
                             __nv_bfloat16* __restrict__ hi,
                             __nv_bfloat16* __restrict__ lo, size_t n4) {
    size_t stride = (size_t)gridDim.x * blockDim.x;
    for (size_t i = (size_t)blockIdx.x * blockDim.x + threadIdx.x; i < n4; i += stride) {
        float4 v = ((const float4*)src)[i];
        uint32_t h0 = pack_bf16x2(v.x, v.y);
        uint32_t h1 = pack_bf16x2(v.z, v.w);
        uint32_t l0 = pack_bf16x2(v.x - __uint_as_float(h0 << 16),
                                  v.y - __uint_as_float(h0 & 0xffff0000u));
        uint32_t l1 = pack_bf16x2(v.z - __uint_as_float(h1 << 16),
                                  v.w - __uint_as_float(h1 & 0xffff0000u));
        ((uint2*)hi)[i] = make_uint2(h0, h1);
        ((uint2*)lo)[i] = make_uint2(l0, l1);
    }
}

// ---------------- 1. ROI max-pool: 4 channels per thread (4x MLP) -----------
__global__ void __launch_bounds__(512) roipool_kernel(const float* __restrict__ feat,
                               const float* __restrict__ rois,
                               const int* __restrict__ roi_idx) {
    int r = blockIdx.x;
    __shared__ int hs[7], he[7], ws[7], we[7];
    if (threadIdx.x == 0) {
        const float RECIP7 = 1.0f / 7.0f;   // matches XLA's x/7 -> x*recip rewrite
        float y1 = rois[r * 4 + 0], x1 = rois[r * 4 + 1];
        float y2 = rois[r * 4 + 2], x2 = rois[r * 4 + 3];
        float sw = rintf(x1 * 0.0625f);
        float ew = rintf(x2 * 0.0625f);
        float sh = rintf(y1 * 0.0625f);
        float eh = rintf(y2 * 0.0625f);
        float rw = fmaxf(ew - sw + 1.0f, 1.0f);
        float rh = fmaxf(eh - sh + 1.0f, 1.0f);
        #pragma unroll
        for (int p = 0; p < 7; p++) {
            float fp = (float)p;
            float h0 = floorf(__fmul_rn(fp * rh, RECIP7)) + sh;
            float h1 = ceilf(__fmul_rn((fp + 1.0f) * rh, RECIP7)) + sh;
            float w0 = floorf(__fmul_rn(fp * rw, RECIP7)) + sw;
            float w1 = ceilf(__fmul_rn((fp + 1.0f) * rw, RECIP7)) + sw;
            hs[p] = (int)fminf(fmaxf(h0, 0.0f), (float)HF);
            he[p] = (int)fminf(fmaxf(h1, 0.0f), (float)HF);
            ws[p] = (int)fminf(fmaxf(w0, 0.0f), (float)WF);
            we[p] = (int)fminf(fmaxf(w1, 0.0f), (float)WF);
        }
    }
    __syncthreads();
    int b = roi_idx[r];
    const float* f = feat + (size_t)b * NCH * HF * WF;
    // each thread does the same window for 4 channels: c, c+128, c+256, c+384
    for (int idx = threadIdx.x; idx < POOLDIM / 4; idx += blockDim.x) {
        int c = idx / 49;                       // 0..127
        int rem = idx - c * 49;
        int ph = rem / 7, pw = rem - (rem / 7) * 7;
        int h0 = hs[ph], h1 = he[ph], w0 = ws[pw], w1 = we[pw];
        float m0 = 0.0f, m1 = 0.0f, m2 = 0.0f, m3 = 0.0f;
        if (h1 > h0 && w1 > w0) {
            m0 = m1 = m2 = m3 = neg_inf();
            const float* f0 = f + (size_t)(c +   0) * (HF * WF);
            const float* f1 = f + (size_t)(c + 128) * (HF * WF);
            const float* f2 = f + (size_t)(c + 256) * (HF * WF);
            const float* f3 = f + (size_t)(c + 384) * (HF * WF);
            for (int y = h0; y < h1; y++) {
                for (int x = w0; x < w1; x++) {
                    int off = y * WF + x;
                    m0 = fmaxf(m0, f0[off]);
                    m1 = fmaxf(m1, f1[off]);
                    m2 = fmaxf(m2, f2[off]);
                    m3 = fmaxf(m3, f3[off]);
                }
            }
        }
        size_t base = (size_t)r * POOLDIM + rem;
        float mm[4] = {m0, m1, m2, m3};
        #pragma unroll
        for (int q = 0; q < 4; q++) {
            size_t o = base + (size_t)(c + q * 128) * 49;
            __nv_bfloat16 hb = __float2bfloat16(mm[q]);
            g_poolh[o] = hb;
            g_pooll[o] = __float2bfloat16(mm[q] - __bfloat162float(hb));
        }
    }
}

// ---------------- 2. head W transpose: g_Wt[55][4096] ----------------------
__global__ void prep_head_kernel(const float* __restrict__ Wloc,
                                 const float* __restrict__ Wsc) {
    int stride = gridDim.x * blockDim.x;
    for (int i = blockIdx.x * blockDim.x + threadIdx.x; i < 55 * FCDIM; i += stride) {
        int col = i >> 12;
        int k = i & (FCDIM - 1);
        g_Wt[i] = (col < 44) ? Wloc[(size_t)k * 44 + col] : Wsc[(size_t)k * 11 + (col - 44)];
    }
}

// ---------------- 3. heads: 2 ROIs per block, warp-per-output --------------
__global__ void __launch_bounds__(256) head_kernel(const float* __restrict__ bloc,
                                                   const float* __restrict__ bsc) {
    __shared__ float4 Fs[2][FCDIM / 4];
    int r0 = blockIdx.x * 2;
    int t = threadIdx.x;
    for (int i = t; i < 2 * (FCDIM / 4); i += 256) {
        int ri = i >> 10, kk = i & 1023;
        Fs[ri][kk] = ((const float4*)g_fc7)[(size_t)(r0 + ri) * (FCDIM / 4) + kk];
    }
    __syncthreads();
    int w = t >> 5, lane = t & 31;
    for (int o = w; o < 110; o += 8) {
        int roi = (o >= 55) ? 1 : 0;
        int col = o - roi * 55;
        const float4* wp = (const float4*)(g_Wt + col * FCDIM);
        float acc = 0.0f;
        for (int kb = lane; kb < FCDIM / 4; kb += 32) {
            float4 f = Fs[roi][kb];
            float4 v = wp[kb];
            acc = fmaf(f.x, v.x, acc);
            acc = fmaf(f.y, v.y, acc);
            acc = fmaf(f.z, v.z, acc);
            acc = fmaf(f.w, v.w, acc);
        }
        #pragma unroll
        for (int of = 16; of > 0; of >>= 1) acc += __shfl_xor_sync(0xffffffffu, acc, of);
        if (lane == 0) {
            float bb = (col < 44) ? bloc[col] : bsc[col - 44];
            g_ls[(r0 + roi) * 55 + col] = acc + bb;
        }
    }
}

// ---------------- 4. bbox decode + clip + softmax ---------------------------
__global__ void post_kernel(const float* __restrict__ rois, float* __restrict__ out) {
    int r = blockIdx.x * blockDim.x + threadIdx.x;
    if (r >= NROI) return;
    float y1 = rois[r * 4 + 0], x1 = rois[r * 4 + 1];
    float y2 = rois[r * 4 + 2], x2 = rois[r * 4 + 3];
    float sh_ = y2 - y1, sw_ = x2 - x1;
    float cy = y1 + 0.5f * sh_, cx = x1 + 0.5f * sw_;
    #pragma unroll
    for (int c = 0; c < NCLS; c++) {
        float dy = g_ls[r * 55 + c * 4 + 0] * 0.1f;
        float dx = g_ls[r * 55 + c * 4 + 1] * 0.1f;
        float dh = g_ls[r * 55 + c * 4 + 2] * 0.2f;
        float dw = g_ls[r * 55 + c * 4 + 3] * 0.2f;
        float ncy = dy * sh_ + cy;
        float ncx = dx * sw_ + cx;
        float nh = expf(dh) * sh_;
        float nw = expf(dw) * sw_;
        float by1 = fminf(fmaxf(ncy - 0.5f * nh, 0.0f), 600.0f);
        float bx1 = fminf(fmaxf(ncx - 0.5f * nw, 0.0f), 800.0f);
        float by2 = fminf(fmaxf(ncy + 0.5f * nh, 0.0f), 600.0f);
        float bx2 = fminf(fmaxf(ncx + 0.5f * nw, 0.0f), 800.0f);
        g_bbox[r * 44 + c * 4 + 0] = by1;
        g_bbox[r * 44 + c * 4 + 1] = bx1;
        g_bbox[r * 44 + c * 4 + 2] = by2;
        g_bbox[r * 44 + c * 4 + 3] = bx2;
        out[r * 44 + c * 4 + 0] = by1;
        out[r * 44 + c * 4 + 1] = bx1;
        out[r * 44 + c * 4 + 2] = by2;
        out[r * 44 + c * 4 + 3] = bx2;
    }
    float sc[NCLS];
    float mx = neg_inf();
    #pragma unroll
    for (int c = 0; c < NCLS; c++) {
        sc[c] = g_ls[r * 55 + 44 + c];
        mx = fmaxf(mx, sc[c]);
    }
    float sum = 0.0f;
    #pragma unroll
    for (int c = 0; c < NCLS; c++) { sc[c] = expf(sc[c] - mx); sum += sc[c]; }
    #pragma unroll
    for (int c = 0; c < NCLS; c++) {
        float p = sc[c] / sum;
        g_prob[r * 11 + c] = p;
        out[NROI * 44 + r * 11 + c] = p;
    }
}

// ---------------- 5. per-class NMS ------------------------------------------
__global__ void __launch_bounds__(512) nms_kernel(float* __restrict__ out) {
    int cls = blockIdx.x + 1;
    int j = threadIdx.x;
    __shared__ float key[NROI];
    __shared__ int order[NROI];
    __shared__ float4 sb[NROI];
    __shared__ unsigned char keep[NROI];

    float s = g_prob[j * 11 + cls];
    bool valid = s > 0.05f;
    float kj = valid ? -s : pos_inf();
    key[j] = kj;
    __syncthreads();
    int rank = 0;
    for (int i = 0; i < NROI; i++) {
        float ki = key[i];
        rank += (ki < kj) || (ki == kj && i < j);
    }
    order[rank] = j;
    __syncthreads();
    int src = order[j];
    float4 box = *(const float4*)&g_bbox[src * 44 + cls * 4];
    sb[j] = box;
    keep[j] = (g_prob[src * 11 + cls] > 0.05f) ? 1 : 0;
    __syncthreads();

    float areaJ = (box.z - box.x) * (box.w - box.y);
    for (int i = 0; i < NROI - 1; i++) {
        if (keep[i] && j > i && keep[j]) {
            float4 bi = sb[i];
            float ty_ = fmaxf(box.x, bi.x);
            float tx_ = fmaxf(box.y, bi.y);
            float by_ = fminf(box.z, bi.z);
            float bx_ = fminf(box.w, bi.w);
            float ih = fmaxf(by_ - ty_, 0.0f);
            float iw = fmaxf(bx_ - tx_, 0.0f);
            float inter = ih * iw;
            float areaI = (bi.z - bi.x) * (bi.w - bi.y);
            float iou = inter / (areaJ + areaI - inter);
            if (iou > 0.3f) keep[j] = 0;
        }
        __syncthreads();
    }
    out[NROI * 44 + NROI * 11 + blockIdx.x * NROI + src] = keep[j] ? 1.0f : 0.0f;
}

// ---------------- launch (exact R11 schedule) --------------------------------
extern "C" void kernel_launch(void* const* d_in, const int* in_sizes, int n_in,
                              void* d_out, int out_size) {
    (void)in_sizes; (void)n_in; (void)out_size;
    const float* h    = (const float*)d_in[0];
    const float* rois = (const float*)d_in[1];
    const int*   ridx = (const int*)d_in[2];
    const float* W1   = (const float*)d_in[3];
    const float* b1   = (const float*)d_in[4];
    const float* W2   = (const float*)d_in[5];
    const float* b2   = (const float*)d_in[6];
    const float* Wloc = (const float*)d_in[7];
    const float* bloc = (const float*)d_in[8];
    const float* Wsc  = (const float*)d_in[9];
    const float* bsc  = (const float*)d_in[10];
    float* out = (float*)d_out;

    void *p_ph, *p_pl, *p_w1h, *p_w1l, *p_w2h, *p_w2l, *p_f1h, *p_f1l, *p_f7, *p_part;
    cudaGetSymbolAddress(&p_ph, g_poolh);
    cudaGetSymbolAddress(&p_pl, g_pooll);
    cudaGetSymbolAddress(&p_w1h, g_W1h);
    cudaGetSymbolAddress(&p_w1l, g_W1l);
    cudaGetSymbolAddress(&p_w2h, g_W2h);
    cudaGetSymbolAddress(&p_w2l, g_W2l);
    cudaGetSymbolAddress(&p_f1h, g_fc1h);
    cudaGetSymbolAddress(&p_f1l, g_fc1l);
    cudaGetSymbolAddress(&p_f7, g_fc7);
    cudaGetSymbolAddress(&p_part, g_part);

    cudaFuncSetAttribute(mma_fc_kernel,
                         cudaFuncAttributeMaxDynamicSharedMemorySize, GEMM_SMEM);

    const int total = NROI * FCDIM;            // 2M elements
    const int redBlocks = total / 4 / 256;     // 2048

    // ---- fork: splits on side streams, roipool on default ----
    cudaEventRecord(g_sp.ev0, 0);
    cudaStreamWaitEvent(g_sp.s1, g_sp.ev0, 0);
    cudaStreamWaitEvent(g_sp.s2, g_sp.ev0, 0);

    split_kernel<<<4096, 256, 0, g_sp.s1>>>(W1, (__nv_bfloat16*)p_w1h,       // 0
        (__nv_bfloat16*)p_w1l, (size_t)POOLDIM * FCDIM / 4);
    split_kernel<<<2048, 256, 0, g_sp.s2>>>(W2, (__nv_bfloat16*)p_w2h,       // 1
        (__nv_bfloat16*)p_w2l, (size_t)FCDIM * FCDIM / 4);
    roipool_kernel<<<NROI, 512>>>(h, rois, ridx);                            // 2

    cudaEventRecord(g_sp.ev1, g_sp.s1);
    cudaEventRecord(g_sp.ev2, g_sp.s2);
    cudaStreamWaitEvent(0, g_sp.ev1, 0);
    cudaStreamWaitEvent(0, g_sp.ev2, 0);

    // ---- joined: GEMMs on default stream ----
    dim3 grid(FCDIM / 128, NROI / 128, NSPLIT);   // (32, 4, 8) = 1024 CTAs
    mma_fc_kernel<<<grid, GEMM_THREADS, GEMM_SMEM>>>(                        // 3 (profiled)
        (const __nv_bfloat16*)p_ph, (const __nv_bfloat16*)p_pl,
        (const __nv_bfloat16*)p_w1h, (const __nv_bfloat16*)p_w1l,
        (float*)p_part, FCDIM, POOLDIM, POOLDIM / NSPLIT);

    // prep_head runs concurrently with GEMM1 on s2 (independent of it)
    prep_head_kernel<<<256, 256, 0, g_sp.s2>>>(Wloc, Wsc);                   // 4
    cudaEventRecord(g_sp.ev3, g_sp.s2);

    reduce_kernel<1><<<redBlocks, 256>>>(                                    // 5
        (const float*)p_part, b1, nullptr,
        (__nv_bfloat16*)p_f1h, (__nv_bfloat16*)p_f1l, FCDIM, total);
    mma_fc_kernel<<<grid, GEMM_THREADS, GEMM_SMEM>>>(                        // 6
        (const __nv_bfloat16*)p_f1h, (const __nv_bfloat16*)p_f1l,
        (const __nv_bfloat16*)p_w2h, (const __nv_bfloat16*)p_w2l,
        (float*)p_part, FCDIM, FCDIM, FCDIM / NSPLIT);
    reduce_kernel<0><<<redBlocks, 256>>>(                                    // 7
        (const float*)p_part, b2, (float*)p_f7, nullptr, nullptr, FCDIM, total);

    cudaStreamWaitEvent(0, g_sp.ev3, 0);
    head_kernel<<<NROI / 2, 256>>>(bloc, bsc);                               // 8
    post_kernel<<<(NROI + 255) / 256, 256>>>(rois, out);                     // 9
    nms_kernel<<<10, NROI>>>(out);                                           // 10
}

// round 15
// speedup vs baseline: 1.0376x; 1.0143x over previous
#include <cuda_runtime.h>
#include <cuda_bf16.h>
#include <math.h>
#include <stdint.h>

#define NROI 512
#define NCH 512
#define HF 37
#define WF 50
#define NCLS 11
#define POOLDIM 25088   // NCH * 7 * 7
#define FCDIM 4096
#define NSPLIT 8

// ---------------- scratch (device globals; no allocation allowed) ----------
__device__ __nv_bfloat16 g_poolh[(size_t)NROI * POOLDIM];
__device__ __nv_bfloat16 g_pooll[(size_t)NROI * POOLDIM];
__device__ __nv_bfloat16 g_W1h[(size_t)POOLDIM * FCDIM];
__device__ __nv_bfloat16 g_W1l[(size_t)POOLDIM * FCDIM];
__device__ __nv_bfloat16 g_W2h[(size_t)FCDIM * FCDIM];
__device__ __nv_bfloat16 g_W2l[(size_t)FCDIM * FCDIM];
__device__ __nv_bfloat16 g_fc1h[(size_t)NROI * FCDIM];
__device__ __nv_bfloat16 g_fc1l[(size_t)NROI * FCDIM];
__device__ float g_part[(size_t)NSPLIT * NROI * FCDIM];   // split-K partials (64MB)
__device__ float g_fc7[(size_t)NROI * FCDIM];
__device__ float g_Wt[55 * FCDIM];
__device__ float g_ls[NROI * 55];
__device__ float g_bbox[NROI * 44];
__device__ float g_prob[NROI * 11];

__device__ __forceinline__ float neg_inf() { return __int_as_float(0xff800000); }
__device__ __forceinline__ float pos_inf() { return __int_as_float(0x7f800000); }

// ---------------- streams/events, created once at static init --------------
struct StreamPack {
    cudaStream_t s1, s2;
    cudaEvent_t ev0, evA, evB, ev2, evPool, evGB, ev3;
    StreamPack() {
        cudaStreamCreateWithFlags(&s1, cudaStreamNonBlocking);
        cudaStreamCreateWithFlags(&s2, cudaStreamNonBlocking);
        cudaEventCreateWithFlags(&ev0, cudaEventDisableTiming);
        cudaEventCreateWithFlags(&evA, cudaEventDisableTiming);
        cudaEventCreateWithFlags(&evB, cudaEventDisableTiming);
        cudaEventCreateWithFlags(&ev2, cudaEventDisableTiming);
        cudaEventCreateWithFlags(&evPool, cudaEventDisableTiming);
        cudaEventCreateWithFlags(&evGB, cudaEventDisableTiming);
        cudaEventCreateWithFlags(&ev3, cudaEventDisableTiming);
    }
};
static StreamPack g_sp;

// ========================= PTX helpers (baseline ISA only) =================
__device__ __forceinline__ uint32_t smem_u32(const void* p) {
    uint32_t a;
    asm("{ .reg .u64 t; cvta.to.shared.u64 t, %1; cvt.u32.u64 %0, t; }" : "=r"(a) : "l"(p));
    return a;
}
__device__ __forceinline__ uint32_t pack_bf16x2(float lo, float hi) {
    uint32_t r;
    asm("cvt.rn.bf16x2.f32 %0, %1, %2;" : "=r"(r) : "f"(hi), "f"(lo));
    return r;
}

#define LDM_X4(r, a) \
    asm volatile("ldmatrix.sync.aligned.m8n8.x4.shared.b16 {%0,%1,%2,%3}, [%4];" \
        : "=r"((r)[0]), "=r"((r)[1]), "=r"((r)[2]), "=r"((r)[3]) : "r"(a))
#define LDM_X4T(r, a) \
    asm volatile("ldmatrix.sync.aligned.m8n8.x4.trans.shared.b16 {%0,%1,%2,%3}, [%4];" \
        : "=r"((r)[0]), "=r"((r)[1]), "=r"((r)[2]), "=r"((r)[3]) : "r"(a))

__device__ __forceinline__ void mma16816(float* c, const uint32_t* a, uint32_t b0, uint32_t b1) {
    asm volatile(
        "mma.sync.aligned.m16n8k16.row.col.f32.bf16.bf16.f32 "
        "{%0,%1,%2,%3}, {%4,%5,%6,%7}, {%8,%9}, {%0,%1,%2,%3};"
        : "+f"(c[0]), "+f"(c[1]), "+f"(c[2]), "+f"(c[3])
        : "r"(a[0]), "r"(a[1]), "r"(a[2]), "r"(a[3]), "r"(b0), "r"(b1));
}

#define CP16(dst, src) \
    asm volatile("cp.async.cg.shared.global [%0], [%1], 16;" :: "r"(dst), "l"(src))
#define CP_COMMIT() asm volatile("cp.async.commit_group;" ::: "memory")
#define CP_WAIT0() asm volatile("cp.async.wait_group 0;" ::: "memory")
#define CP_WAIT1() asm volatile("cp.async.wait_group 1;" ::: "memory")
#define CP_WAIT2() asm volatile("cp.async.wait_group 2;" ::: "memory")

// ========================= split-bf16 HMMA GEMM (R7/R11 core + split-K) ====
// Partial[z] = A[:, zKs:(z+1)Ks] * B[zKs:(z+1)Ks, :]; 3-pass hh+hl+lh.
// Tile 128x128x32, 512 threads (16 warps, warp tile 32x32), 4-stage cp.async.
#define ST_AHI 0
#define ST_ALO 8192
#define ST_BHI 16384
#define ST_BLO 24576
#define STAGE_SZ 32768
#define NSTAGE 4
#define GEMM_SMEM (NSTAGE * STAGE_SZ)
#define GEMM_THREADS 512

__device__ __forceinline__ uint32_t aoff(int m, int k) {
    return (uint32_t)(m * 64 + ((((k >> 3) ^ ((m >> 1) ^ (m >> 3))) & 3) << 4) + (k & 7) * 2);
}
__device__ __forceinline__ uint32_t boff(int k, int n) {
    return (uint32_t)(k * 256 + ((((n >> 3) ^ (k & 7)) & 15) << 4) + (n & 7) * 2);
}

__global__ void __launch_bounds__(GEMM_THREADS, 1)
mma_fc_kernel(const __nv_bfloat16* __restrict__ Ah, const __nv_bfloat16* __restrict__ Al,
              const __nv_bfloat16* __restrict__ Bh, const __nv_bfloat16* __restrict__ Bl,
              float* __restrict__ Cpart, int N, int Ktot, int Ks) {
    extern __shared__ char smem[];
    uint32_t sbase = smem_u32(smem);
    const int t = threadIdx.x;
    const int lane = t & 31;
    const int wid = t >> 5;
    const int wy = wid & 3;
    const int wx = wid >> 2;
    const int m0 = blockIdx.y * 128;
    const int n0 = blockIdx.x * 128;
    const int kbase = blockIdx.z * Ks;

    const int am = t >> 2;
    const int ak = (t & 3) * 8;
    const int bk = t >> 4;
    const int bn = (t & 15) * 8;

    const uint32_t oA = ST_AHI + aoff(am, ak);
    const uint32_t oB = ST_BHI + boff(bk, bn);

    const int nit = Ks / 32;

    float acc[2][4][4];
    #pragma unroll
    for (int i = 0; i < 2; i++)
        #pragma unroll
        for (int j = 0; j < 4; j++)
            #pragma unroll
            for (int e = 0; e < 4; e++) acc[i][j][e] = 0.0f;

#define ISSUE(stg, kg) do {                                                    \
        uint32_t s_ = sbase + (uint32_t)(stg) * STAGE_SZ;                      \
        const __nv_bfloat16* ah_ = Ah + (size_t)(m0 + am) * Ktot + (kg) + ak;  \
        const __nv_bfloat16* al_ = Al + (size_t)(m0 + am) * Ktot + (kg) + ak;  \
        CP16(s_ + oA, ah_);                                                    \
        CP16(s_ + oA + (ST_ALO - ST_AHI), al_);                                \
        const __nv_bfloat16* bh_ = Bh + (size_t)((kg) + bk) * N + n0 + bn;     \
        const __nv_bfloat16* bl_ = Bl + (size_t)((kg) + bk) * N + n0 + bn;     \
        CP16(s_ + oB, bh_);                                                    \
        CP16(s_ + oB + (ST_BLO - ST_BHI), bl_);                                \
        CP_COMMIT();                                                           \
    } while (0)

    ISSUE(0, kbase);
    ISSUE(1, kbase + 32);
    ISSUE(2, kbase + 64);

    const int arow_l = lane & 15;
    const int khalf = (lane >> 4) << 3;

    int cur = 0, nxt = 3;
    for (int it = 0; it < nit; it++) {
        if (it < nit - 2)      { CP_WAIT2(); }
        else if (it == nit - 2){ CP_WAIT1(); }
        else                   { CP_WAIT0(); }
        __syncthreads();
        if (it + 3 < nit) {
            ISSUE(nxt, kbase + (it + 3) * 32);
            if (++nxt == NSTAGE) nxt = 0;
        }

        uint32_t sA_hi = sbase + (uint32_t)cur * STAGE_SZ + ST_AHI;
        uint32_t sA_lo = sA_hi + (ST_ALO - ST_AHI);
        uint32_t sB_hi = sbase + (uint32_t)cur * STAGE_SZ + ST_BHI;
        uint32_t sB_lo = sB_hi + (ST_BLO - ST_BHI);
        if (++cur == NSTAGE) cur = 0;

        #pragma unroll
        for (int ks = 0; ks < 2; ks++) {
            const int k0 = ks * 16;
            uint32_t ah[2][4], al[2][4], bh[2][4], bl[2][4];
            #pragma unroll
            for (int mi = 0; mi < 2; mi++) {
                int mrow = wy * 32 + mi * 16 + arow_l;
                uint32_t oa = aoff(mrow, k0 + khalf);
                LDM_X4(ah[mi], sA_hi + oa);
                LDM_X4(al[mi], sA_lo + oa);
            }
            #pragma unroll
            for (int nt = 0; nt < 2; nt++) {
                int krow = k0 + (lane & 15);
                int ncol = wx * 32 + nt * 16 + khalf;
                uint32_t ob = boff(krow, ncol);
                LDM_X4T(bh[nt], sB_hi + ob);
                LDM_X4T(bl[nt], sB_lo + ob);
            }
            // pass-major: RAW distance between same-acc MMAs is 8
            #pragma unroll
            for (int mi = 0; mi < 2; mi++)
                #pragma unroll
                for (int ni = 0; ni < 4; ni++)
                    mma16816(acc[mi][ni], ah[mi], bh[ni >> 1][(ni & 1) * 2],
                             bh[ni >> 1][(ni & 1) * 2 + 1]);
            #pragma unroll
            for (int mi = 0; mi < 2; mi++)
                #pragma unroll
                for (int ni = 0; ni < 4; ni++)
                    mma16816(acc[mi][ni], ah[mi], bl[ni >> 1][(ni & 1) * 2],
                             bl[ni >> 1][(ni & 1) * 2 + 1]);
            #pragma unroll
            for (int mi = 0; mi < 2; mi++)
                #pragma unroll
                for (int ni = 0; ni < 4; ni++)
                    mma16816(acc[mi][ni], al[mi], bh[ni >> 1][(ni & 1) * 2],
                             bh[ni >> 1][(ni & 1) * 2 + 1]);
        }
    }

    // ---- epilogue: raw fp32 partial store ----
    float* Cp = Cpart + (size_t)blockIdx.z * (size_t)(gridDim.y * 128) * N;
    #pragma unroll
    for (int mi = 0; mi < 2; mi++) {
        int mrow = m0 + wy * 32 + mi * 16 + (lane >> 2);
        #pragma unroll
        for (int ni = 0; ni < 4; ni++) {
            int ncol = n0 + wx * 32 + ni * 8 + (lane & 3) * 2;
            *(float2*)(Cp + (size_t)mrow * N + ncol) =
                make_float2(acc[mi][ni][0], acc[mi][ni][1]);
            *(float2*)(Cp + (size_t)(mrow + 8) * N + ncol) =
                make_float2(acc[mi][ni][2], acc[mi][ni][3]);
        }
    }
#undef ISSUE
}

// ---------------- split-K reduce: sum partials + bias + relu ---------------
template <int OUT>
__global__ void __launch_bounds__(256) reduce_kernel(
        const float* __restrict__ part, const float* __restrict__ bias,
        float* __restrict__ Cf, __nv_bfloat16* __restrict__ Ch,
        __nv_bfloat16* __restrict__ Cl, int N, int total) {
    int i4 = blockIdx.x * blockDim.x + threadIdx.x;   // float4 index
    if (i4 * 4 >= total) return;
    float4 s = ((const float4*)part)[i4];
    #pragma unroll
    for (int z = 1; z < NSPLIT; z++) {
        float4 p = ((const float4*)(part + (size_t)z * total))[i4];
        s.x += p.x; s.y += p.y; s.z += p.z; s.w += p.w;
    }
    int e = i4 * 4;
    int n = e & (N - 1);
    s.x = fmaxf(s.x + bias[n],     0.0f);
    s.y = fmaxf(s.y + bias[n + 1], 0.0f);
    s.z = fmaxf(s.z + bias[n + 2], 0.0f);
    s.w = fmaxf(s.w + bias[n + 3], 0.0f);
    if (OUT == 0) {
        ((float4*)Cf)[i4] = s;
    } else {
        uint32_t h01 = pack_bf16x2(s.x, s.y);
        uint32_t h23 = pack_bf16x2(s.z, s.w);
        uint32_t l01 = pack_bf16x2(s.x - __uint_as_float(h01 << 16),
                                   s.y - __uint_as_float(h01 & 0xffff0000u));
        uint32_t l23 = pack_bf16x2(s.z - __uint_as_float(h23 << 16),
                                   s.w - __uint_as_float(h23 & 0xffff0000u));
        ((uint2*)Ch)[i4] = make_uint2(h01, h23);
        ((uint2*)Cl)[i4] = make_uint2(l01, l23);
    }
}

// ---------------- 0. fp32 -> bf16 hi/lo split (streaming) -------------------
__global__ void split_kernel(const float* __restrict__ src,
                             __nv_bfloat16* __restrict__ hi,
                             __nv_bfloat16* __restrict__ lo, size_t n4) {
    size_t stride = (size_t)gridDim.x * blockDim.x;
    for (size_t i = (size_t)blockIdx.x * blockDim.x + threadIdx.x; i < n4; i += stride) {
        float4 v = ((const float4*)src)[i];
        uint32_t h0 = pack_bf16x2(v.x, v.y);
        uint32_t h1 = pack_bf16x2(v.z, v.w);
        uint32_t l0 = pack_bf16x2(v.x - __uint_as_float(h0 << 16),
                                  v.y - __uint_as_float(h0 & 0xffff0000u));
        uint32_t l1 = pack_bf16x2(v.z - __uint_as_float(h1 << 16),
                                  v.w - __uint_as_float(h1 & 0xffff0000u));
        ((uint2*)hi)[i] = make_uint2(h0, h1);
        ((uint2*)lo)[i] = make_uint2(l0, l1);
    }
}

// ---------------- 1. ROI max-pool: 4 channels per thread (4x MLP) -----------
__global__ void __launch_bounds__(512) roipool_kernel(const float* __restrict__ feat,
                               const float* __restrict__ rois,
                               const int* __restrict__ roi_idx) {
    int r = blockIdx.x;
    __shared__ int hs[7], he[7], ws[7], we[7];
    if (threadIdx.x == 0) {
        const float RECIP7 = 1.0f / 7.0f;   // matches XLA's x/7 -> x*recip rewrite
        float y1 = rois[r * 4 + 0], x1 = rois[r * 4 + 1];
        float y2 = rois[r * 4 + 2], x2 = rois[r * 4 + 3];
        float sw = rintf(x1 * 0.0625f);
        float ew = rintf(x2 * 0.0625f);
        float sh = rintf(y1 * 0.0625f);
        float eh = rintf(y2 * 0.0625f);
        float rw = fmaxf(ew - sw + 1.0f, 1.0f);
        float rh = fmaxf(eh - sh + 1.0f, 1.0f);
        #pragma unroll
        for (int p = 0; p < 7; p++) {
            float fp = (float)p;
            float h0 = floorf(__fmul_rn(fp * rh, RECIP7)) + sh;
            float h1 = ceilf(__fmul_rn((fp + 1.0f) * rh, RECIP7)) + sh;
            float w0 = floorf(__fmul_rn(fp * rw, RECIP7)) + sw;
            float w1 = ceilf(__fmul_rn((fp + 1.0f) * rw, RECIP7)) + sw;
            hs[p] = (int)fminf(fmaxf(h0, 0.0f), (float)HF);
            he[p] = (int)fminf(fmaxf(h1, 0.0f), (float)HF);
            ws[p] = (int)fminf(fmaxf(w0, 0.0f), (float)WF);
            we[p] = (int)fminf(fmaxf(w1, 0.0f), (float)WF);
        }
    }
    __syncthreads();
    int b = roi_idx[r];
    const float* f = feat + (size_t)b * NCH * HF * WF;
    for (int idx = threadIdx.x; idx < POOLDIM / 4; idx += blockDim.x) {
        int c = idx / 49;                       // 0..127
        int rem = idx - c * 49;
        int ph = rem / 7, pw = rem - (rem / 7) * 7;
        int h0 = hs[ph], h1 = he[ph], w0 = ws[pw], w1 = we[pw];
        float m0 = 0.0f, m1 = 0.0f, m2 = 0.0f, m3 = 0.0f;
        if (h1 > h0 && w1 > w0) {
            m0 = m1 = m2 = m3 = neg_inf();
            const float* f0 = f + (size_t)(c +   0) * (HF * WF);
            const float* f1 = f + (size_t)(c + 128) * (HF * WF);
            const float* f2 = f + (size_t)(c + 256) * (HF * WF);
            const float* f3 = f + (size_t)(c + 384) * (HF * WF);
            for (int y = h0; y < h1; y++) {
                for (int x = w0; x < w1; x++) {
                    int off = y * WF + x;
                    m0 = fmaxf(m0, f0[off]);
                    m1 = fmaxf(m1, f1[off]);
                    m2 = fmaxf(m2, f2[off]);
                    m3 = fmaxf(m3, f3[off]);
                }
            }
        }
        size_t base = (size_t)r * POOLDIM + rem;
        float mm[4] = {m0, m1, m2, m3};
        #pragma unroll
        for (int q = 0; q < 4; q++) {
            size_t o = base + (size_t)(c + q * 128) * 49;
            __nv_bfloat16 hb = __float2bfloat16(mm[q]);
            g_poolh[o] = hb;
            g_pooll[o] = __float2bfloat16(mm[q] - __bfloat162float(hb));
        }
    }
}

// ---------------- 2. head W transpose: g_Wt[55][4096] ----------------------
__global__ void prep_head_kernel(const float* __restrict__ Wloc,
                                 const float* __restrict__ Wsc) {
    int stride = gridDim.x * blockDim.x;
    for (int i = blockIdx.x * blockDim.x + threadIdx.x; i < 55 * FCDIM; i += stride) {
        int col = i >> 12;
        int k = i & (FCDIM - 1);
        g_Wt[i] = (col < 44) ? Wloc[(size_t)k * 44 + col] : Wsc[(size_t)k * 11 + (col - 44)];
    }
}

// ---------------- 3. heads: 2 ROIs per block, warp-per-output --------------
__global__ void __launch_bounds__(256) head_kernel(const float* __restrict__ bloc,
                                                   const float* __restrict__ bsc) {
    __shared__ float4 Fs[2][FCDIM / 4];
    int r0 = blockIdx.x * 2;
    int t = threadIdx.x;
    for (int i = t; i < 2 * (FCDIM / 4); i += 256) {
        int ri = i >> 10, kk = i & 1023;
        Fs[ri][kk] = ((const float4*)g_fc7)[(size_t)(r0 + ri) * (FCDIM / 4) + kk];
    }
    __syncthreads();
    int w = t >> 5, lane = t & 31;
    for (int o = w; o < 110; o += 8) {
        int roi = (o >= 55) ? 1 : 0;
        int col = o - roi * 55;
        const float4* wp = (const float4*)(g_Wt + col * FCDIM);
        float acc = 0.0f;
        for (int kb = lane; kb < FCDIM / 4; kb += 32) {
            float4 f = Fs[roi][kb];
            float4 v = wp[kb];
            acc = fmaf(f.x, v.x, acc);
            acc = fmaf(f.y, v.y, acc);
            acc = fmaf(f.z, v.z, acc);
            acc = fmaf(f.w, v.w, acc);
        }
        #pragma unroll
        for (int of = 16; of > 0; of >>= 1) acc += __shfl_xor_sync(0xffffffffu, acc, of);
        if (lane == 0) {
            float bb = (col < 44) ? bloc[col] : bsc[col - 44];
            g_ls[(r0 + roi) * 55 + col] = acc + bb;
        }
    }
}

// ---------------- 4. bbox decode + clip + softmax ---------------------------
__global__ void post_kernel(const float* __restrict__ rois, float* __restrict__ out) {
    int r = blockIdx.x * blockDim.x + threadIdx.x;
    if (r >= NROI) return;
    float y1 = rois[r * 4 + 0], x1 = rois[r * 4 + 1];
    float y2 = rois[r * 4 + 2], x2 = rois[r * 4 + 3];
    float sh_ = y2 - y1, sw_ = x2 - x1;
    float cy = y1 + 0.5f * sh_, cx = x1 + 0.5f * sw_;
    #pragma unroll
    for (int c = 0; c < NCLS; c++) {
        float dy = g_ls[r * 55 + c * 4 + 0] * 0.1f;
        float dx = g_ls[r * 55 + c * 4 + 1] * 0.1f;
        float dh = g_ls[r * 55 + c * 4 + 2] * 0.2f;
        float dw = g_ls[r * 55 + c * 4 + 3] * 0.2f;
        float ncy = dy * sh_ + cy;
        float ncx = dx * sw_ + cx;
        float nh = expf(dh) * sh_;
        float nw = expf(dw) * sw_;
        float by1 = fminf(fmaxf(ncy - 0.5f * nh, 0.0f), 600.0f);
        float bx1 = fminf(fmaxf(ncx - 0.5f * nw, 0.0f), 800.0f);
        float by2 = fminf(fmaxf(ncy + 0.5f * nh, 0.0f), 600.0f);
        float bx2 = fminf(fmaxf(ncx + 0.5f * nw, 0.0f), 800.0f);
        g_bbox[r * 44 + c * 4 + 0] = by1;
        g_bbox[r * 44 + c * 4 + 1] = bx1;
        g_bbox[r * 44 + c * 4 + 2] = by2;
        g_bbox[r * 44 + c * 4 + 3] = bx2;
        out[r * 44 + c * 4 + 0] = by1;
        out[r * 44 + c * 4 + 1] = bx1;
        out[r * 44 + c * 4 + 2] = by2;
        out[r * 44 + c * 4 + 3] = bx2;
    }
    float sc[NCLS];
    float mx = neg_inf();
    #pragma unroll
    for (int c = 0; c < NCLS; c++) {
        sc[c] = g_ls[r * 55 + 44 + c];
        mx = fmaxf(mx, sc[c]);
    }
    float sum = 0.0f;
    #pragma unroll
    for (int c = 0; c < NCLS; c++) { sc[c] = expf(sc[c] - mx); sum += sc[c]; }
    #pragma unroll
    for (int c = 0; c < NCLS; c++) {
        float p = sc[c] / sum;
        g_prob[r * 11 + c] = p;
        out[NROI * 44 + r * 11 + c] = p;
    }
}

// ---------------- 5. per-class NMS ------------------------------------------
__global__ void __launch_bounds__(512) nms_kernel(float* __restrict__ out) {
    int cls = blockIdx.x + 1;
    int j = threadIdx.x;
    __shared__ float key[NROI];
    __shared__ int order[NROI];
    __shared__ float4 sb[NROI];
    __shared__ unsigned char keep[NROI];

    float s = g_prob[j * 11 + cls];
    bool valid = s > 0.05f;
    float kj = valid ? -s : pos_inf();
    key[j] = kj;
    __syncthreads();
    int rank = 0;
    for (int i = 0; i < NROI; i++) {
        float ki = key[i];
        rank += (ki < kj) || (ki == kj && i < j);
    }
    order[rank] = j;
    __syncthreads();
    int src = order[j];
    float4 box = *(const float4*)&g_bbox[src * 44 + cls * 4];
    sb[j] = box;
    keep[j] = (g_prob[src * 11 + cls] > 0.05f) ? 1 : 0;
    __syncthreads();

    float areaJ = (box.z - box.x) * (box.w - box.y);
    for (int i = 0; i < NROI - 1; i++) {
        if (keep[i] && j > i && keep[j]) {
            float4 bi = sb[i];
            float ty_ = fmaxf(box.x, bi.x);
            float tx_ = fmaxf(box.y, bi.y);
            float by_ = fminf(box.z, bi.z);
            float bx_ = fminf(box.w, bi.w);
            float ih = fmaxf(by_ - ty_, 0.0f);
            float iw = fmaxf(bx_ - tx_, 0.0f);
            float inter = ih * iw;
            float areaI = (bi.z - bi.x) * (bi.w - bi.y);
            float iou = inter / (areaJ + areaI - inter);
            if (iou > 0.3f) keep[j] = 0;
        }
        __syncthreads();
    }
    out[NROI * 44 + NROI * 11 + blockIdx.x * NROI + src] = keep[j] ? 1.0f : 0.0f;
}

// ---------------- launch ----------------------------------------------------
extern "C" void kernel_launch(void* const* d_in, const int* in_sizes, int n_in,
                              void* d_out, int out_size) {
    (void)in_sizes; (void)n_in; (void)out_size;
    const float* h    = (const float*)d_in[0];
    const float* rois = (const float*)d_in[1];
    const int*   ridx = (const int*)d_in[2];
    const float* W1   = (const float*)d_in[3];
    const float* b1   = (const float*)d_in[4];
    const float* W2   = (const float*)d_in[5];
    const float* b2   = (const float*)d_in[6];
    const float* Wloc = (const float*)d_in[7];
    const float* bloc = (const float*)d_in[8];
    const float* Wsc  = (const float*)d_in[9];
    const float* bsc  = (const float*)d_in[10];
    float* out = (float*)d_out;

    void *p_ph, *p_pl, *p_w1h, *p_w1l, *p_w2h, *p_w2l, *p_f1h, *p_f1l, *p_f7, *p_part;
    cudaGetSymbolAddress(&p_ph, g_poolh);
    cudaGetSymbolAddress(&p_pl, g_pooll);
    cudaGetSymbolAddress(&p_w1h, g_W1h);
    cudaGetSymbolAddress(&p_w1l, g_W1l);
    cudaGetSymbolAddress(&p_w2h, g_W2h);
    cudaGetSymbolAddress(&p_w2l, g_W2l);
    cudaGetSymbolAddress(&p_f1h, g_fc1h);
    cudaGetSymbolAddress(&p_f1l, g_fc1l);
    cudaGetSymbolAddress(&p_f7, g_fc7);
    cudaGetSymbolAddress(&p_part, g_part);

    cudaFuncSetAttribute(mma_fc_kernel,
                         cudaFuncAttributeMaxDynamicSharedMemorySize, GEMM_SMEM);

    const int total = NROI * FCDIM;                 // 2M elements
    const int redBlocks = total / 4 / 256;          // 2048
    const int Ks = POOLDIM / NSPLIT;                // 3136
    const int Khalf = POOLDIM / 2;                  // 12544 (= 4*Ks)
    const size_t halfW1 = (size_t)Khalf * FCDIM;    // element offset into W1 splits

    const __nv_bfloat16* ph = (const __nv_bfloat16*)p_ph;
    const __nv_bfloat16* pl = (const __nv_bfloat16*)p_pl;
    const __nv_bfloat16* w1h = (const __nv_bfloat16*)p_w1h;
    const __nv_bfloat16* w1l = (const __nv_bfloat16*)p_w1l;

    // ---- fork ----
    cudaEventRecord(g_sp.ev0, 0);
    cudaStreamWaitEvent(g_sp.s1, g_sp.ev0, 0);
    cudaStreamWaitEvent(g_sp.s2, g_sp.ev0, 0);

    // split W1 first K-half on s1                                            // 0
    split_kernel<<<2048, 256, 0, g_sp.s1>>>(W1, (__nv_bfloat16*)p_w1h,
        (__nv_bfloat16*)p_w1l, halfW1 / 4);
    cudaEventRecord(g_sp.evA, g_sp.s1);

    // split W2 on s2                                                          // 1
    split_kernel<<<2048, 256, 0, g_sp.s2>>>(W2, (__nv_bfloat16*)p_w2h,
        (__nv_bfloat16*)p_w2l, (size_t)FCDIM * FCDIM / 4);
    cudaEventRecord(g_sp.ev2, g_sp.s2);

    // roipool on default                                                      // 2
    roipool_kernel<<<NROI, 512>>>(h, rois, ridx);
    cudaEventRecord(g_sp.evPool, 0);

    // ---- GEMM1-A: K[0, 12544), z=0..3, waits only on split half-1 ----
    cudaStreamWaitEvent(0, g_sp.evA, 0);
    dim3 gridH(FCDIM / 128, NROI / 128, NSPLIT / 2);   // (32, 4, 4) = 512 CTAs
    mma_fc_kernel<<<gridH, GEMM_THREADS, GEMM_SMEM>>>(                        // 3 (profiled)
        ph, pl, w1h, w1l, (float*)p_part, FCDIM, POOLDIM, Ks);

    // split W1 second K-half on s1                                            // 4
    split_kernel<<<2048, 256, 0, g_sp.s1>>>(W1 + halfW1,
        (__nv_bfloat16*)p_w1h + halfW1, (__nv_bfloat16*)p_w1l + halfW1, halfW1 / 4);
    cudaEventRecord(g_sp.evB, g_sp.s1);

    // ---- GEMM1-B: K[12544, 25088), z=0..3 with pointer offsets, on s2 ----
    cudaStreamWaitEvent(g_sp.s2, g_sp.evB, 0);
    cudaStreamWaitEvent(g_sp.s2, g_sp.evPool, 0);
    mma_fc_kernel<<<gridH, GEMM_THREADS, GEMM_SMEM, g_sp.s2>>>(               // 5
        ph + Khalf, pl + Khalf, w1h + halfW1, w1l + halfW1,
        (float*)p_part + (size_t)4 * total, FCDIM, POOLDIM, Ks);
    cudaEventRecord(g_sp.evGB, g_sp.s2);

    // prep_head after GEMM1-B on s2 (hidden under default-stream GEMM work)
    prep_head_kernel<<<256, 256, 0, g_sp.s2>>>(Wloc, Wsc);                    // 6
    cudaEventRecord(g_sp.ev3, g_sp.s2);

    // ---- reduce1 needs both GEMM1 halves ----
    cudaStreamWaitEvent(0, g_sp.evGB, 0);
    reduce_kernel<1><<<redBlocks, 256>>>(                                     // 7
        (const float*)p_part, b1, nullptr,
        (__nv_bfloat16*)p_f1h, (__nv_bfloat16*)p_f1l, FCDIM, total);

    // ---- GEMM2 (full split-K, needs W2) ----
    cudaStreamWaitEvent(0, g_sp.ev2, 0);
    dim3 gridF(FCDIM / 128, NROI / 128, NSPLIT);       // (32, 4, 8)
    mma_fc_kernel<<<gridF, GEMM_THREADS, GEMM_SMEM>>>(                        // 8
        (const __nv_bfloat16*)p_f1h, (const __nv_bfloat16*)p_f1l,
        (const __nv_bfloat16*)p_w2h, (const __nv_bfloat16*)p_w2l,
        (float*)p_part, FCDIM, FCDIM, FCDIM / NSPLIT);
    reduce_kernel<0><<<redBlocks, 256>>>(                                     // 9
        (const float*)p_part, b2, (float*)p_f7, nullptr, nullptr, FCDIM, total);

    cudaStreamWaitEvent(0, g_sp.ev3, 0);
    head_kernel<<<NROI / 2, 256>>>(bloc, bsc);                                // 10
    post_kernel<<<(NROI + 255) / 256, 256>>>(rois, out);                      // 11
    nms_kernel<<<10, NROI>>>(out);                                            // 12
}

// round 16
// speedup vs baseline: 1.0459x; 1.0081x over previous
#include <cuda_runtime.h>
#include <cuda_bf16.h>
#include <math.h>
#include <stdint.h>

#define NROI 512
#define NCH 512
#define HF 37
#define WF 50
#define NCLS 11
#define POOLDIM 25088   // NCH * 7 * 7
#define FCDIM 4096
#define NSPLIT 8

// ---------------- scratch (device globals; no allocation allowed) ----------
__device__ __nv_bfloat16 g_poolh[(size_t)NROI * POOLDIM];
__device__ __nv_bfloat16 g_pooll[(size_t)NROI * POOLDIM];
__device__ __nv_bfloat16 g_W1h[(size_t)POOLDIM * FCDIM];
__device__ __nv_bfloat16 g_W1l[(size_t)POOLDIM * FCDIM];
__device__ __nv_bfloat16 g_W2h[(size_t)FCDIM * FCDIM];
__device__ __nv_bfloat16 g_W2l[(size_t)FCDIM * FCDIM];
__device__ __nv_bfloat16 g_fc1h[(size_t)NROI * FCDIM];
__device__ __nv_bfloat16 g_fc1l[(size_t)NROI * FCDIM];
__device__ float g_part[(size_t)NSPLIT * NROI * FCDIM];   // split-K partials (64MB)
__device__ float g_fc7[(size_t)NROI * FCDIM];
__device__ float g_Wt[55 * FCDIM];
__device__ float g_ls[NROI * 55];
__device__ float g_bbox[NROI * 44];
__device__ float g_prob[NROI * 11];

__device__ __forceinline__ float neg_inf() { return __int_as_float(0xff800000); }
__device__ __forceinline__ float pos_inf() { return __int_as_float(0x7f800000); }

// ---------------- streams/events, created once at static init --------------
struct StreamPack {
    cudaStream_t s1, s2;
    cudaEvent_t ev0, evA, evB, ev2, evPool, evGB, ev3;
    StreamPack() {
        cudaStreamCreateWithFlags(&s1, cudaStreamNonBlocking);
        cudaStreamCreateWithFlags(&s2, cudaStreamNonBlocking);
        cudaEventCreateWithFlags(&ev0, cudaEventDisableTiming);
        cudaEventCreateWithFlags(&evA, cudaEventDisableTiming);
        cudaEventCreateWithFlags(&evB, cudaEventDisableTiming);
        cudaEventCreateWithFlags(&ev2, cudaEventDisableTiming);
        cudaEventCreateWithFlags(&evPool, cudaEventDisableTiming);
        cudaEventCreateWithFlags(&evGB, cudaEventDisableTiming);
        cudaEventCreateWithFlags(&ev3, cudaEventDisableTiming);
    }
};
static StreamPack g_sp;

// ========================= PTX helpers (baseline ISA only) =================
__device__ __forceinline__ uint32_t smem_u32(const void* p) {
    uint32_t a;
    asm("{ .reg .u64 t; cvta.to.shared.u64 t, %1; cvt.u32.u64 %0, t; }" : "=r"(a) : "l"(p));
    return a;
}
__device__ __forceinline__ uint32_t pack_bf16x2(float lo, float hi) {
    uint32_t r;
    asm("cvt.rn.bf16x2.f32 %0, %1, %2;" : "=r"(r) : "f"(hi), "f"(lo));
    return r;
}

#define LDM_X4(r, a) \
    asm volatile("ldmatrix.sync.aligned.m8n8.x4.shared.b16 {%0,%1,%2,%3}, [%4];" \
        : "=r"((r)[0]), "=r"((r)[1]), "=r"((r)[2]), "=r"((r)[3]) : "r"(a))
#define LDM_X4T(r, a) \
    asm volatile("ldmatrix.sync.aligned.m8n8.x4.trans.shared.b16 {%0,%1,%2,%3}, [%4];" \
        : "=r"((r)[0]), "=r"((r)[1]), "=r"((r)[2]), "=r"((r)[3]) : "r"(a))

__device__ __forceinline__ void mma16816(float* c, const uint32_t* a, uint32_t b0, uint32_t b1) {
    asm volatile(
        "mma.sync.aligned.m16n8k16.row.col.f32.bf16.bf16.f32 "
        "{%0,%1,%2,%3}, {%4,%5,%6,%7}, {%8,%9}, {%0,%1,%2,%3};"
        : "+f"(c[0]), "+f"(c[1]), "+f"(c[2]), "+f"(c[3])
        : "r"(a[0]), "r"(a[1]), "r"(a[2]), "r"(a[3]), "r"(b0), "r"(b1));
}

#define CP16(dst, src) \
    asm volatile("cp.async.cg.shared.global [%0], [%1], 16;" :: "r"(dst), "l"(src))
#define CP_COMMIT() asm volatile("cp.async.commit_group;" ::: "memory")
#define CP_WAIT0() asm volatile("cp.async.wait_group 0;" ::: "memory")
#define CP_WAIT1() asm volatile("cp.async.wait_group 1;" ::: "memory")
#define CP_WAIT2() asm volatile("cp.async.wait_group 2;" ::: "memory")

// ========================= split-bf16 HMMA GEMM (R7/R11 core + split-K) ====
// Partial[z] = A[:, zKs:(z+1)Ks] * B[zKs:(z+1)Ks, :]; 3-pass hh+hl+lh.
// Tile 128x128x32, 512 threads (16 warps, warp tile 32x32), 4-stage cp.async.
#define ST_AHI 0
#define ST_ALO 8192
#define ST_BHI 16384
#define ST_BLO 24576
#define STAGE_SZ 32768
#define NSTAGE 4
#define GEMM_SMEM (NSTAGE * STAGE_SZ)
#define GEMM_THREADS 512

__device__ __forceinline__ uint32_t aoff(int m, int k) {
    return (uint32_t)(m * 64 + ((((k >> 3) ^ ((m >> 1) ^ (m >> 3))) & 3) << 4) + (k & 7) * 2);
}
__device__ __forceinline__ uint32_t boff(int k, int n) {
    return (uint32_t)(k * 256 + ((((n >> 3) ^ (k & 7)) & 15) << 4) + (n & 7) * 2);
}

__global__ void __launch_bounds__(GEMM_THREADS, 1)
mma_fc_kernel(const __nv_bfloat16* __restrict__ Ah, const __nv_bfloat16* __restrict__ Al,
              const __nv_bfloat16* __restrict__ Bh, const __nv_bfloat16* __restrict__ Bl,
              float* __restrict__ Cpart, int N, int Ktot, int Ks) {
    extern __shared__ char smem[];
    uint32_t sbase = smem_u32(smem);
    const int t = threadIdx.x;
    const int lane = t & 31;
    const int wid = t >> 5;
    const int wy = wid & 3;
    const int wx = wid >> 2;
    const int m0 = blockIdx.y * 128;
    const int n0 = blockIdx.x * 128;
    const int kbase = blockIdx.z * Ks;

    const int am = t >> 2;
    const int ak = (t & 3) * 8;
    const int bk = t >> 4;
    const int bn = (t & 15) * 8;

    const uint32_t oA = ST_AHI + aoff(am, ak);
    const uint32_t oB = ST_BHI + boff(bk, bn);

    const int nit = Ks / 32;

    float acc[2][4][4];
    #pragma unroll
    for (int i = 0; i < 2; i++)
        #pragma unroll
        for (int j = 0; j < 4; j++)
            #pragma unroll
            for (int e = 0; e < 4; e++) acc[i][j][e] = 0.0f;

#define ISSUE(stg, kg) do {                                                    \
        uint32_t s_ = sbase + (uint32_t)(stg) * STAGE_SZ;                      \
        const __nv_bfloat16* ah_ = Ah + (size_t)(m0 + am) * Ktot + (kg) + ak;  \
        const __nv_bfloat16* al_ = Al + (size_t)(m0 + am) * Ktot + (kg) + ak;  \
        CP16(s_ + oA, ah_);                                                    \
        CP16(s_ + oA + (ST_ALO - ST_AHI), al_);                                \
        const __nv_bfloat16* bh_ = Bh + (size_t)((kg) + bk) * N + n0 + bn;     \
        const __nv_bfloat16* bl_ = Bl + (size_t)((kg) + bk) * N + n0 + bn;     \
        CP16(s_ + oB, bh_);                                                    \
        CP16(s_ + oB + (ST_BLO - ST_BHI), bl_);                                \
        CP_COMMIT();                                                           \
    } while (0)

    ISSUE(0, kbase);
    ISSUE(1, kbase + 32);
    ISSUE(2, kbase + 64);

    const int arow_l = lane & 15;
    const int khalf = (lane >> 4) << 3;

    int cur = 0, nxt = 3;
    for (int it = 0; it < nit; it++) {
        if (it < nit - 2)      { CP_WAIT2(); }
        else if (it == nit - 2){ CP_WAIT1(); }
        else                   { CP_WAIT0(); }
        __syncthreads();
        if (it + 3 < nit) {
            ISSUE(nxt, kbase + (it + 3) * 32);
            if (++nxt == NSTAGE) nxt = 0;
        }

        uint32_t sA_hi = sbase + (uint32_t)cur * STAGE_SZ + ST_AHI;
        uint32_t sA_lo = sA_hi + (ST_ALO - ST_AHI);
        uint32_t sB_hi = sbase + (uint32_t)cur * STAGE_SZ + ST_BHI;
        uint32_t sB_lo = sB_hi + (ST_BLO - ST_BHI);
        if (++cur == NSTAGE) cur = 0;

        #pragma unroll
        for (int ks = 0; ks < 2; ks++) {
            const int k0 = ks * 16;
            uint32_t ah[2][4], al[2][4], bh[2][4], bl[2][4];
            #pragma unroll
            for (int mi = 0; mi < 2; mi++) {
                int mrow = wy * 32 + mi * 16 + arow_l;
                uint32_t oa = aoff(mrow, k0 + khalf);
                LDM_X4(ah[mi], sA_hi + oa);
                LDM_X4(al[mi], sA_lo + oa);
            }
            #pragma unroll
            for (int nt = 0; nt < 2; nt++) {
                int krow = k0 + (lane & 15);
                int ncol = wx * 32 + nt * 16 + khalf;
                uint32_t ob = boff(krow, ncol);
                LDM_X4T(bh[nt], sB_hi + ob);
                LDM_X4T(bl[nt], sB_lo + ob);
            }
            // pass-major: RAW distance between same-acc MMAs is 8
            #pragma unroll
            for (int mi = 0; mi < 2; mi++)
                #pragma unroll
                for (int ni = 0; ni < 4; ni++)
                    mma16816(acc[mi][ni], ah[mi], bh[ni >> 1][(ni & 1) * 2],
                             bh[ni >> 1][(ni & 1) * 2 + 1]);
            #pragma unroll
            for (int mi = 0; mi < 2; mi++)
                #pragma unroll
                for (int ni = 0; ni < 4; ni++)
                    mma16816(acc[mi][ni], ah[mi], bl[ni >> 1][(ni & 1) * 2],
                             bl[ni >> 1][(ni & 1) * 2 + 1]);
            #pragma unroll
            for (int mi = 0; mi < 2; mi++)
                #pragma unroll
                for (int ni = 0; ni < 4; ni++)
                    mma16816(acc[mi][ni], al[mi], bh[ni >> 1][(ni & 1) * 2],
                             bh[ni >> 1][(ni & 1) * 2 + 1]);
        }
    }

    // ---- epilogue: raw fp32 partial store ----
    float* Cp = Cpart + (size_t)blockIdx.z * (size_t)(gridDim.y * 128) * N;
    #pragma unroll
    for (int mi = 0; mi < 2; mi++) {
        int mrow = m0 + wy * 32 + mi * 16 + (lane >> 2);
        #pragma unroll
        for (int ni = 0; ni < 4; ni++) {
            int ncol = n0 + wx * 32 + ni * 8 + (lane & 3) * 2;
            *(float2*)(Cp + (size_t)mrow * N + ncol) =
                make_float2(acc[mi][ni][0], acc[mi][ni][1]);
            *(float2*)(Cp + (size_t)(mrow + 8) * N + ncol) =
                make_float2(acc[mi][ni][2], acc[mi][ni][3]);
        }
    }
#undef ISSUE
}

// ---------------- split-K reduce: sum partials + bias + relu ---------------
template <int OUT>
__global__ void __launch_bounds__(256) reduce_kernel(
        const float* __restrict__ part, const float* __restrict__ bias,
        float* __restrict__ Cf, __nv_bfloat16* __restrict__ Ch,
        __nv_bfloat16* __restrict__ Cl, int N, int total) {
    int i4 = blockIdx.x * blockDim.x + threadIdx.x;   // float4 index
    if (i4 * 4 >= total) return;
    float4 s = ((const float4*)part)[i4];
    #pragma unroll
    for (int z = 1; z < NSPLIT; z++) {
        float4 p = ((const float4*)(part + (size_t)z * total))[i4];
        s.x += p.x; s.y += p.y; s.z += p.z; s.w += p.w;
    }
    int e = i4 * 4;
    int n = e & (N - 1);
    s.x = fmaxf(s.x + bias[n],     0.0f);
    s.y = fmaxf(s.y + bias[n + 1], 0.0f);
    s.z = fmaxf(s.z + bias[n + 2], 0.0f);
    s.w = fmaxf(s.w + bias[n + 3], 0.0f);
    if (OUT == 0) {
        ((float4*)Cf)[i4] = s;
    } else {
        uint32_t h01 = pack_bf16x2(s.x, s.y);
        uint32_t h23 = pack_bf16x2(s.z, s.w);
        uint32_t l01 = pack_bf16x2(s.x - __uint_as_float(h01 << 16),
                                   s.y - __uint_as_float(h01 & 0xffff0000u));
        uint32_t l23 = pack_bf16x2(s.z - __uint_as_float(h23 << 16),
                                   s.w - __uint_as_float(h23 & 0xffff0000u));
        ((uint2*)Ch)[i4] = make_uint2(h01, h23);
        ((uint2*)Cl)[i4] = make_uint2(l01, l23);
    }
}

// ---------------- 0. fp32 -> bf16 hi/lo split (streaming) -------------------
__global__ void split_kernel(const float* __restrict__ src,
                             __nv_bfloat16* __restrict__ hi,
                             __nv_bfloat16* __restrict__ lo, size_t n4) {
    size_t stride = (size_t)gridDim.x * blockDim.x;
    for (size_t i = (size_t)blockIdx.x * blockDim.x + threadIdx.x; i < n4; i += stride) {
        float4 v = ((const float4*)src)[i];
        uint32_t h0 = pack_bf16x2(v.x, v.y);
        uint32_t h1 = pack_bf16x2(v.z, v.w);
        uint32_t l0 = pack_bf16x2(v.x - __uint_as_float(h0 << 16),
                                  v.y - __uint_as_float(h0 & 0xffff0000u));
        uint32_t l1 = pack_bf16x2(v.z - __uint_as_float(h1 << 16),
                                  v.w - __uint_as_float(h1 & 0xffff0000u));
        ((uint2*)hi)[i] = make_uint2(h0, h1);
        ((uint2*)lo)[i] = make_uint2(l0, l1);
    }
}

// ---------------- 1. ROI max-pool: 4 channels per thread (4x MLP) -----------
__global__ void __launch_bounds__(512) roipool_kernel(const float* __restrict__ feat,
                               const float* __restrict__ rois,
                               const int* __restrict__ roi_idx) {
    int r = blockIdx.x;
    __shared__ int hs[7], he[7], ws[7], we[7];
    if (threadIdx.x == 0) {
        const float RECIP7 = 1.0f / 7.0f;   // matches XLA's x/7 -> x*recip rewrite
        float y1 = rois[r * 4 + 0], x1 = rois[r * 4 + 1];
        float y2 = rois[r * 4 + 2], x2 = rois[r * 4 + 3];
        float sw = rintf(x1 * 0.0625f);
        float ew = rintf(x2 * 0.0625f);
        float sh = rintf(y1 * 0.0625f);
        float eh = rintf(y2 * 0.0625f);
        float rw = fmaxf(ew - sw + 1.0f, 1.0f);
        float rh = fmaxf(eh - sh + 1.0f, 1.0f);
        #pragma unroll
        for (int p = 0; p < 7; p++) {
            float fp = (float)p;
            float h0 = floorf(__fmul_rn(fp * rh, RECIP7)) + sh;
            float h1 = ceilf(__fmul_rn((fp + 1.0f) * rh, RECIP7)) + sh;
            float w0 = floorf(__fmul_rn(fp * rw, RECIP7)) + sw;
            float w1 = ceilf(__fmul_rn((fp + 1.0f) * rw, RECIP7)) + sw;
            hs[p] = (int)fminf(fmaxf(h0, 0.0f), (float)HF);
            he[p] = (int)fminf(fmaxf(h1, 0.0f), (float)HF);
            ws[p] = (int)fminf(fmaxf(w0, 0.0f), (float)WF);
            we[p] = (int)fminf(fmaxf(w1, 0.0f), (float)WF);
        }
    }
    __syncthreads();
    int b = roi_idx[r];
    const float* f = feat + (size_t)b * NCH * HF * WF;
    for (int idx = threadIdx.x; idx < POOLDIM / 4; idx += blockDim.x) {
        int c = idx / 49;                       // 0..127
        int rem = idx - c * 49;
        int ph = rem / 7, pw = rem - (rem / 7) * 7;
        int h0 = hs[ph], h1 = he[ph], w0 = ws[pw], w1 = we[pw];
        float m0 = 0.0f, m1 = 0.0f, m2 = 0.0f, m3 = 0.0f;
        if (h1 > h0 && w1 > w0) {
            m0 = m1 = m2 = m3 = neg_inf();
            const float* f0 = f + (size_t)(c +   0) * (HF * WF);
            const float* f1 = f + (size_t)(c + 128) * (HF * WF);
            const float* f2 = f + (size_t)(c + 256) * (HF * WF);
            const float* f3 = f + (size_t)(c + 384) * (HF * WF);
            for (int y = h0; y < h1; y++) {
                for (int x = w0; x < w1; x++) {
                    int off = y * WF + x;
                    m0 = fmaxf(m0, f0[off]);
                    m1 = fmaxf(m1, f1[off]);
                    m2 = fmaxf(m2, f2[off]);
                    m3 = fmaxf(m3, f3[off]);
                }
            }
        }
        size_t base = (size_t)r * POOLDIM + rem;
        float mm[4] = {m0, m1, m2, m3};
        #pragma unroll
        for (int q = 0; q < 4; q++) {
            size_t o = base + (size_t)(c + q * 128) * 49;
            __nv_bfloat16 hb = __float2bfloat16(mm[q]);
            g_poolh[o] = hb;
            g_pooll[o] = __float2bfloat16(mm[q] - __bfloat162float(hb));
        }
    }
}

// ---------------- 2. head W transpose: g_Wt[55][4096] ----------------------
__global__ void prep_head_kernel(const float* __restrict__ Wloc,
                                 const float* __restrict__ Wsc) {
    int stride = gridDim.x * blockDim.x;
    for (int i = blockIdx.x * blockDim.x + threadIdx.x; i < 55 * FCDIM; i += stride) {
        int col = i >> 12;
        int k = i & (FCDIM - 1);
        g_Wt[i] = (col < 44) ? Wloc[(size_t)k * 44 + col] : Wsc[(size_t)k * 11 + (col - 44)];
    }
}

// ---------------- 3. heads: 2 ROIs per block, warp-per-output --------------
__global__ void __launch_bounds__(256) head_kernel(const float* __restrict__ bloc,
                                                   const float* __restrict__ bsc) {
    __shared__ float4 Fs[2][FCDIM / 4];
    int r0 = blockIdx.x * 2;
    int t = threadIdx.x;
    for (int i = t; i < 2 * (FCDIM / 4); i += 256) {
        int ri = i >> 10, kk = i & 1023;
        Fs[ri][kk] = ((const float4*)g_fc7)[(size_t)(r0 + ri) * (FCDIM / 4) + kk];
    }
    __syncthreads();
    int w = t >> 5, lane = t & 31;
    for (int o = w; o < 110; o += 8) {
        int roi = (o >= 55) ? 1 : 0;
        int col = o - roi * 55;
        const float4* wp = (const float4*)(g_Wt + col * FCDIM);
        float acc = 0.0f;
        for (int kb = lane; kb < FCDIM / 4; kb += 32) {
            float4 f = Fs[roi][kb];
            float4 v = wp[kb];
            acc = fmaf(f.x, v.x, acc);
            acc = fmaf(f.y, v.y, acc);
            acc = fmaf(f.z, v.z, acc);
            acc = fmaf(f.w, v.w, acc);
        }
        #pragma unroll
        for (int of = 16; of > 0; of >>= 1) acc += __shfl_xor_sync(0xffffffffu, acc, of);
        if (lane == 0) {
            float bb = (col < 44) ? bloc[col] : bsc[col - 44];
            g_ls[(r0 + roi) * 55 + col] = acc + bb;
        }
    }
}

// ---------------- 4. bbox decode + clip + softmax ---------------------------
__global__ void post_kernel(const float* __restrict__ rois, float* __restrict__ out) {
    int r = blockIdx.x * blockDim.x + threadIdx.x;
    if (r >= NROI) return;
    float y1 = rois[r * 4 + 0], x1 = rois[r * 4 + 1];
    float y2 = rois[r * 4 + 2], x2 = rois[r * 4 + 3];
    float sh_ = y2 - y1, sw_ = x2 - x1;
    float cy = y1 + 0.5f * sh_, cx = x1 + 0.5f * sw_;
    #pragma unroll
    for (int c = 0; c < NCLS; c++) {
        float dy = g_ls[r * 55 + c * 4 + 0] * 0.1f;
        float dx = g_ls[r * 55 + c * 4 + 1] * 0.1f;
        float dh = g_ls[r * 55 + c * 4 + 2] * 0.2f;
        float dw = g_ls[r * 55 + c * 4 + 3] * 0.2f;
        float ncy = dy * sh_ + cy;
        float ncx = dx * sw_ + cx;
        float nh = expf(dh) * sh_;
        float nw = expf(dw) * sw_;
        float by1 = fminf(fmaxf(ncy - 0.5f * nh, 0.0f), 600.0f);
        float bx1 = fminf(fmaxf(ncx - 0.5f * nw, 0.0f), 800.0f);
        float by2 = fminf(fmaxf(ncy + 0.5f * nh, 0.0f), 600.0f);
        float bx2 = fminf(fmaxf(ncx + 0.5f * nw, 0.0f), 800.0f);
        g_bbox[r * 44 + c * 4 + 0] = by1;
        g_bbox[r * 44 + c * 4 + 1] = bx1;
        g_bbox[r * 44 + c * 4 + 2] = by2;
        g_bbox[r * 44 + c * 4 + 3] = bx2;
        out[r * 44 + c * 4 + 0] = by1;
        out[r * 44 + c * 4 + 1] = bx1;
        out[r * 44 + c * 4 + 2] = by2;
        out[r * 44 + c * 4 + 3] = bx2;
    }
    float sc[NCLS];
    float mx = neg_inf();
    #pragma unroll
    for (int c = 0; c < NCLS; c++) {
        sc[c] = g_ls[r * 55 + 44 + c];
        mx = fmaxf(mx, sc[c]);
    }
    float sum = 0.0f;
    #pragma unroll
    for (int c = 0; c < NCLS; c++) { sc[c] = expf(sc[c] - mx); sum += sc[c]; }
    #pragma unroll
    for (int c = 0; c < NCLS; c++) {
        float p = sc[c] / sum;
        g_prob[r * 11 + c] = p;
        out[NROI * 44 + r * 11 + c] = p;
    }
}

// ---------------- 5. per-class NMS ------------------------------------------
__global__ void __launch_bounds__(512) nms_kernel(float* __restrict__ out) {
    int cls = blockIdx.x + 1;
    int j = threadIdx.x;
    __shared__ float key[NROI];
    __shared__ int order[NROI];
    __shared__ float4 sb[NROI];
    __shared__ unsigned char keep[NROI];

    float s = g_prob[j * 11 + cls];
    bool valid = s > 0.05f;
    float kj = valid ? -s : pos_inf();
    key[j] = kj;
    __syncthreads();
    int rank = 0;
    for (int i = 0; i < NROI; i++) {
        float ki = key[i];
        rank += (ki < kj) || (ki == kj && i < j);
    }
    order[rank] = j;
    __syncthreads();
    int src = order[j];
    float4 box = *(const float4*)&g_bbox[src * 44 + cls * 4];
    sb[j] = box;
    keep[j] = (g_prob[src * 11 + cls] > 0.05f) ? 1 : 0;
    __syncthreads();

    float areaJ = (box.z - box.x) * (box.w - box.y);
    for (int i = 0; i < NROI - 1; i++) {
        if (keep[i] && j > i && keep[j]) {
            float4 bi = sb[i];
            float ty_ = fmaxf(box.x, bi.x);
            float tx_ = fmaxf(box.y, bi.y);
            float by_ = fminf(box.z, bi.z);
            float bx_ = fminf(box.w, bi.w);
            float ih = fmaxf(by_ - ty_, 0.0f);
            float iw = fmaxf(bx_ - tx_, 0.0f);
            float inter = ih * iw;
            float areaI = (bi.z - bi.x) * (bi.w - bi.y);
            float iou = inter / (areaJ + areaI - inter);
            if (iou > 0.3f) keep[j] = 0;
        }
        __syncthreads();
    }
    out[NROI * 44 + NROI * 11 + blockIdx.x * NROI + src] = keep[j] ? 1.0f : 0.0f;
}

// ---------------- launch ----------------------------------------------------
extern "C" void kernel_launch(void* const* d_in, const int* in_sizes, int n_in,
                              void* d_out, int out_size) {
    (void)in_sizes; (void)n_in; (void)out_size;
    const float* h    = (const float*)d_in[0];
    const float* rois = (const float*)d_in[1];
    const int*   ridx = (const int*)d_in[2];
    const float* W1   = (const float*)d_in[3];
    const float* b1   = (const float*)d_in[4];
    const float* W2   = (const float*)d_in[5];
    const float* b2   = (const float*)d_in[6];
    const float* Wloc = (const float*)d_in[7];
    const float* bloc = (const float*)d_in[8];
    const float* Wsc  = (const float*)d_in[9];
    const float* bsc  = (const float*)d_in[10];
    float* out = (float*)d_out;

    void *p_ph, *p_pl, *p_w1h, *p_w1l, *p_w2h, *p_w2l, *p_f1h, *p_f1l, *p_f7, *p_part;
    cudaGetSymbolAddress(&p_ph, g_poolh);
    cudaGetSymbolAddress(&p_pl, g_pooll);
    cudaGetSymbolAddress(&p_w1h, g_W1h);
    cudaGetSymbolAddress(&p_w1l, g_W1l);
    cudaGetSymbolAddress(&p_w2h, g_W2h);
    cudaGetSymbolAddress(&p_w2l, g_W2l);
    cudaGetSymbolAddress(&p_f1h, g_fc1h);
    cudaGetSymbolAddress(&p_f1l, g_fc1l);
    cudaGetSymbolAddress(&p_f7, g_fc7);
    cudaGetSymbolAddress(&p_part, g_part);

    cudaFuncSetAttribute(mma_fc_kernel,
                         cudaFuncAttributeMaxDynamicSharedMemorySize, GEMM_SMEM);

    const int total = NROI * FCDIM;                 // 2M elements
    const int redBlocks = total / 4 / 256;          // 2048
    const int Ks = POOLDIM / NSPLIT;                // 3136
    const int Kq = POOLDIM / 4;                     // 6272 (= 2*Ks)
    const size_t qW1 = (size_t)Kq * FCDIM;          // element offset into W1 splits

    const __nv_bfloat16* ph = (const __nv_bfloat16*)p_ph;
    const __nv_bfloat16* pl = (const __nv_bfloat16*)p_pl;
    const __nv_bfloat16* w1h = (const __nv_bfloat16*)p_w1h;
    const __nv_bfloat16* w1l = (const __nv_bfloat16*)p_w1l;

    // ---- fork ----
    cudaEventRecord(g_sp.ev0, 0);
    cudaStreamWaitEvent(g_sp.s1, g_sp.ev0, 0);
    cudaStreamWaitEvent(g_sp.s2, g_sp.ev0, 0);

    // split W1 first K-quarter on s1                                         // 0
    split_kernel<<<2048, 256, 0, g_sp.s1>>>(W1, (__nv_bfloat16*)p_w1h,
        (__nv_bfloat16*)p_w1l, qW1 / 4);
    cudaEventRecord(g_sp.evA, g_sp.s1);

    // split W2 on s2                                                          // 1
    split_kernel<<<2048, 256, 0, g_sp.s2>>>(W2, (__nv_bfloat16*)p_w2h,
        (__nv_bfloat16*)p_w2l, (size_t)FCDIM * FCDIM / 4);
    cudaEventRecord(g_sp.ev2, g_sp.s2);

    // roipool on default                                                      // 2
    roipool_kernel<<<NROI, 512>>>(h, rois, ridx);
    cudaEventRecord(g_sp.evPool, 0);

    // ---- GEMM1-A: K[0, 6272), z=0..1, waits only on split quarter-1 ----
    cudaStreamWaitEvent(0, g_sp.evA, 0);
    dim3 gridA(FCDIM / 128, NROI / 128, 2);            // (32, 4, 2) = 256 CTAs
    mma_fc_kernel<<<gridA, GEMM_THREADS, GEMM_SMEM>>>(                        // 3 (profiled)
        ph, pl, w1h, w1l, (float*)p_part, FCDIM, POOLDIM, Ks);

    // split W1 remaining 3/4 on s1                                            // 4
    split_kernel<<<2048, 256, 0, g_sp.s1>>>(W1 + qW1,
        (__nv_bfloat16*)p_w1h + qW1, (__nv_bfloat16*)p_w1l + qW1, 3 * qW1 / 4);
    cudaEventRecord(g_sp.evB, g_sp.s1);

    // ---- GEMM1-B: K[6272, 25088), z=2..7 with pointer offsets, on s2 ----
    cudaStreamWaitEvent(g_sp.s2, g_sp.evB, 0);
    cudaStreamWaitEvent(g_sp.s2, g_sp.evPool, 0);
    dim3 gridB(FCDIM / 128, NROI / 128, 6);            // (32, 4, 6) = 768 CTAs
    mma_fc_kernel<<<gridB, GEMM_THREADS, GEMM_SMEM, g_sp.s2>>>(               // 5
        ph + Kq, pl + Kq, w1h + qW1, w1l + qW1,
        (float*)p_part + (size_t)2 * total, FCDIM, POOLDIM, Ks);
    cudaEventRecord(g_sp.evGB, g_sp.s2);

    // prep_head after GEMM1-B on s2 (hidden under default-stream GEMM work)
    prep_head_kernel<<<256, 256, 0, g_sp.s2>>>(Wloc, Wsc);                    // 6
    cudaEventRecord(g_sp.ev3, g_sp.s2);

    // ---- reduce1 needs both GEMM1 pieces ----
    cudaStreamWaitEvent(0, g_sp.evGB, 0);
    reduce_kernel<1><<<redBlocks, 256>>>(                                     // 7
        (const float*)p_part, b1, nullptr,
        (__nv_bfloat16*)p_f1h, (__nv_bfloat16*)p_f1l, FCDIM, total);

    // ---- GEMM2 (full split-K, needs W2) ----
    cudaStreamWaitEvent(0, g_sp.ev2, 0);
    dim3 gridF(FCDIM / 128, NROI / 128, NSPLIT);       // (32, 4, 8)
    mma_fc_kernel<<<gridF, GEMM_THREADS, GEMM_SMEM>>>(                        // 8
        (const __nv_bfloat16*)p_f1h, (const __nv_bfloat16*)p_f1l,
        (const __nv_bfloat16*)p_w2h, (const __nv_bfloat16*)p_w2l,
        (float*)p_part, FCDIM, FCDIM, FCDIM / NSPLIT);
    reduce_kernel<0><<<redBlocks, 256>>>(                                     // 9
        (const float*)p_part, b2, (float*)p_f7, nullptr, nullptr, FCDIM, total);

    cudaStreamWaitEvent(0, g_sp.ev3, 0);
    head_kernel<<<NROI / 2, 256>>>(bloc, bsc);                                // 10
    post_kernel<<<(NROI + 255) / 256, 256>>>(rois, out);                      // 11
    nms_kernel<<<10, NROI>>>(out);                                            // 12
}